// round 2
// baseline (speedup 1.0000x reference)
#include <cuda_runtime.h>
#include <cuda_bf16.h>
#include <cstdint>
#include <cstddef>

// ---------------------------------------------------------------------------
// Problem constants
// ---------------------------------------------------------------------------
constexpr int BATCH = 4;
constexpr int TSEQ  = 8192;
constexpr int CDIM  = 2048;
constexpr int NHEAD = 16;
constexpr int DHEAD = 128;
constexpr int NBLK  = 64;            // TSEQ / 128
constexpr int MROWS = BATCH * TSEQ;  // 32768
constexpr int N_QKV = 3 * CDIM;      // 6144

// ---------------------------------------------------------------------------
// Static scratch (no allocations allowed)
// ---------------------------------------------------------------------------
__device__ __align__(256) __nv_bfloat16 g_Xhi [(size_t)MROWS * CDIM];
__device__ __align__(256) __nv_bfloat16 g_Xlo [(size_t)MROWS * CDIM];
__device__ __align__(256) __nv_bfloat16 g_Wqh [(size_t)CDIM * N_QKV];
__device__ __align__(256) __nv_bfloat16 g_Wql [(size_t)CDIM * N_QKV];
__device__ __align__(256) __nv_bfloat16 g_Wph [(size_t)CDIM * CDIM];
__device__ __align__(256) __nv_bfloat16 g_Wpl [(size_t)CDIM * CDIM];
__device__ __align__(256) __nv_bfloat16 g_QKVh[(size_t)MROWS * N_QKV];
__device__ __align__(256) __nv_bfloat16 g_QKVl[(size_t)MROWS * N_QKV];
__device__ __align__(256) __nv_bfloat16 g_ATTh[(size_t)MROWS * CDIM];
__device__ __align__(256) __nv_bfloat16 g_ATTl[(size_t)MROWS * CDIM];

// ---------------------------------------------------------------------------
// Small device helpers
// ---------------------------------------------------------------------------
__device__ __forceinline__ uint32_t pk2(__nv_bfloat16 a, __nv_bfloat16 b) {
    __nv_bfloat162 t; t.x = a; t.y = b;
    return *reinterpret_cast<uint32_t*>(&t);
}

__device__ __forceinline__ void split2(float a, float b, uint32_t& hi, uint32_t& lo) {
    __nv_bfloat16 ha = __float2bfloat16(a);
    __nv_bfloat16 hb = __float2bfloat16(b);
    __nv_bfloat16 la = __float2bfloat16(a - __bfloat162float(ha));
    __nv_bfloat16 lb = __float2bfloat16(b - __bfloat162float(hb));
    hi = pk2(ha, hb);
    lo = pk2(la, lb);
}

__device__ __forceinline__ void cp16(void* s, const void* g) {
    uint32_t sa = (uint32_t)__cvta_generic_to_shared(s);
    asm volatile("cp.async.cg.shared.global [%0], [%1], 16;" :: "r"(sa), "l"(g));
}
__device__ __forceinline__ void cp_commit() {
    asm volatile("cp.async.commit_group;");
}
template <int N>
__device__ __forceinline__ void cp_wait() {
    asm volatile("cp.async.wait_group %0;" :: "n"(N));
}

__device__ __forceinline__ void ldsm4(uint32_t* d, const void* p) {
    uint32_t a = (uint32_t)__cvta_generic_to_shared(p);
    asm volatile("ldmatrix.sync.aligned.m8n8.x4.shared.b16 {%0,%1,%2,%3}, [%4];"
                 : "=r"(d[0]), "=r"(d[1]), "=r"(d[2]), "=r"(d[3]) : "r"(a));
}
__device__ __forceinline__ void ldsm2(uint32_t* d, const void* p) {
    uint32_t a = (uint32_t)__cvta_generic_to_shared(p);
    asm volatile("ldmatrix.sync.aligned.m8n8.x2.shared.b16 {%0,%1}, [%2];"
                 : "=r"(d[0]), "=r"(d[1]) : "r"(a));
}
__device__ __forceinline__ void ldsm2t(uint32_t* d, const void* p) {
    uint32_t a = (uint32_t)__cvta_generic_to_shared(p);
    asm volatile("ldmatrix.sync.aligned.m8n8.x2.trans.shared.b16 {%0,%1}, [%2];"
                 : "=r"(d[0]), "=r"(d[1]) : "r"(a));
}

__device__ __forceinline__ void mma16816(float* c, const uint32_t* a, const uint32_t* b) {
    asm volatile(
        "mma.sync.aligned.m16n8k16.row.col.f32.bf16.bf16.f32 "
        "{%0,%1,%2,%3}, {%4,%5,%6,%7}, {%8,%9}, {%0,%1,%2,%3};"
        : "+f"(c[0]), "+f"(c[1]), "+f"(c[2]), "+f"(c[3])
        : "r"(a[0]), "r"(a[1]), "r"(a[2]), "r"(a[3]), "r"(b[0]), "r"(b[1]));
}

// ---------------------------------------------------------------------------
// Split kernel: fp32 -> (bf16 hi, bf16 lo)
// ---------------------------------------------------------------------------
__global__ void split_kernel(const float4* __restrict__ src,
                             uint32_t* __restrict__ hi,
                             uint32_t* __restrict__ lo, int n4) {
    int i = blockIdx.x * blockDim.x + threadIdx.x;
    if (i >= n4) return;
    float4 v = src[i];
    uint32_t h0, l0, h1, l1;
    split2(v.x, v.y, h0, l0);
    split2(v.z, v.w, h1, l1);
    hi[2 * i]     = h0;
    hi[2 * i + 1] = h1;
    lo[2 * i]     = l0;
    lo[2 * i + 1] = l1;
}

// ---------------------------------------------------------------------------
// Split-bf16 GEMM: C[M,N] = (Ahi+Alo)[M,K] @ (Bhi+Blo)[K,N]
// Tiles: BM=128, BN=128, BK=32. 256 threads, 8 warps (2m x 4n), warp 64x32.
// SPLIT_OUT: write C as bf16 hi/lo; else write fp32.
// ---------------------------------------------------------------------------
__device__ __forceinline__ void gemm_load_tile(
    const __nv_bfloat16* __restrict__ Ahi, const __nv_bfloat16* __restrict__ Alo,
    const __nv_bfloat16* __restrict__ Bhi, const __nv_bfloat16* __restrict__ Blo,
    __nv_bfloat16* sA, __nv_bfloat16* sB,
    int buf, int kt, int m0, int n0, int Nn, int Kk, int tid)
{
    // A tile: [2 planes][128 rows][32 cols], 4 chunks of 16B per row per plane
#pragma unroll
    for (int i = 0; i < 4; i++) {
        int cidx  = tid + i * 256;
        int plane = cidx >> 9;
        int rem   = cidx & 511;
        int r     = rem >> 2;
        int ch    = rem & 3;
        const __nv_bfloat16* g = (plane ? Alo : Ahi) + (size_t)(m0 + r) * Kk + kt * 32 + ch * 8;
        int sw = ch ^ ((r >> 1) & 3);
        __nv_bfloat16* s = sA + ((buf * 2 + plane) * 128 + r) * 32 + sw * 8;
        cp16(s, g);
    }
    // B tile: [2 planes][32 rows][128 cols], 16 chunks per row per plane
#pragma unroll
    for (int i = 0; i < 4; i++) {
        int cidx  = tid + i * 256;
        int plane = cidx >> 9;
        int rem   = cidx & 511;
        int r     = rem >> 4;
        int ch    = rem & 15;
        const __nv_bfloat16* g = (plane ? Blo : Bhi) + (size_t)(kt * 32 + r) * Nn + n0 + ch * 8;
        int sw = ch ^ (r & 7);
        __nv_bfloat16* s = sB + ((buf * 2 + plane) * 32 + r) * 128 + sw * 8;
        cp16(s, g);
    }
}

template <bool SPLIT_OUT>
__global__ void __launch_bounds__(256, 1) gemm_split_kernel(
    const __nv_bfloat16* __restrict__ Ahi, const __nv_bfloat16* __restrict__ Alo,
    const __nv_bfloat16* __restrict__ Bhi, const __nv_bfloat16* __restrict__ Blo,
    __nv_bfloat16* __restrict__ Chi, __nv_bfloat16* __restrict__ Clo,
    float* __restrict__ Cf, int Mm, int Nn, int Kk)
{
    extern __shared__ __nv_bfloat16 smem[];
    __nv_bfloat16* sA = smem;          // 2 buf * 2 plane * 128 * 32 = 16384
    __nv_bfloat16* sB = smem + 16384;  // 2 buf * 2 plane * 32 * 128 = 16384

    const int tid  = threadIdx.x;
    const int lane = tid & 31;
    const int wid  = tid >> 5;
    const int m0   = blockIdx.y * 128;
    const int n0   = blockIdx.x * 128;
    const int wm   = (wid >> 2) * 64;
    const int wn   = (wid & 3) * 32;

    float c[4][4][4];
#pragma unroll
    for (int mt = 0; mt < 4; mt++)
#pragma unroll
        for (int nt = 0; nt < 4; nt++)
#pragma unroll
            for (int e = 0; e < 4; e++) c[mt][nt][e] = 0.f;

    const int nk = Kk / 32;
    gemm_load_tile(Ahi, Alo, Bhi, Blo, sA, sB, 0, 0, m0, n0, Nn, Kk, tid);
    cp_commit();

    for (int kt = 0; kt < nk; kt++) {
        if (kt + 1 < nk) {
            gemm_load_tile(Ahi, Alo, Bhi, Blo, sA, sB, (kt + 1) & 1, kt + 1, m0, n0, Nn, Kk, tid);
            cp_commit();
            cp_wait<1>();
        } else {
            cp_wait<0>();
        }
        __syncthreads();
        const int buf = kt & 1;

#pragma unroll
        for (int kk = 0; kk < 2; kk++) {
            uint32_t aH[4][4], aL[4][4];
#pragma unroll
            for (int mt = 0; mt < 4; mt++) {
                int r  = wm + mt * 16 + (lane & 15);
                int ch = kk * 2 + (lane >> 4);
                int sw = ch ^ ((r >> 1) & 3);
                ldsm4(aH[mt], sA + ((buf * 2 + 0) * 128 + r) * 32 + sw * 8);
                ldsm4(aL[mt], sA + ((buf * 2 + 1) * 128 + r) * 32 + sw * 8);
            }
            uint32_t bH[4][2], bL[4][2];
#pragma unroll
            for (int nt = 0; nt < 4; nt++) {
                int l16  = lane & 15;
                int krow = kk * 16 + l16;
                int ch   = (wn >> 3) + nt;
                int sw   = ch ^ (krow & 7);
                ldsm2t(bH[nt], sB + ((buf * 2 + 0) * 32 + krow) * 128 + sw * 8);
                ldsm2t(bL[nt], sB + ((buf * 2 + 1) * 32 + krow) * 128 + sw * 8);
            }
#pragma unroll
            for (int mt = 0; mt < 4; mt++)
#pragma unroll
                for (int nt = 0; nt < 4; nt++) {
                    mma16816(c[mt][nt], aH[mt], bH[nt]);
                    mma16816(c[mt][nt], aH[mt], bL[nt]);
                    mma16816(c[mt][nt], aL[mt], bH[nt]);
                }
        }
        __syncthreads();
    }

    // Epilogue
#pragma unroll
    for (int mt = 0; mt < 4; mt++) {
#pragma unroll
        for (int nt = 0; nt < 4; nt++) {
            int row = m0 + wm + mt * 16 + (lane >> 2);
            int col = n0 + wn + nt * 8 + (lane & 3) * 2;
            float v0 = c[mt][nt][0], v1 = c[mt][nt][1];
            float v2 = c[mt][nt][2], v3 = c[mt][nt][3];
            if (SPLIT_OUT) {
                uint32_t h, l;
                split2(v0, v1, h, l);
                *reinterpret_cast<uint32_t*>(Chi + (size_t)row * Nn + col) = h;
                *reinterpret_cast<uint32_t*>(Clo + (size_t)row * Nn + col) = l;
                split2(v2, v3, h, l);
                *reinterpret_cast<uint32_t*>(Chi + (size_t)(row + 8) * Nn + col) = h;
                *reinterpret_cast<uint32_t*>(Clo + (size_t)(row + 8) * Nn + col) = l;
            } else {
                float2 p0 = make_float2(v0, v1);
                float2 p1 = make_float2(v2, v3);
                *reinterpret_cast<float2*>(Cf + (size_t)row * Nn + col) = p0;
                *reinterpret_cast<float2*>(Cf + (size_t)(row + 8) * Nn + col) = p1;
            }
        }
    }
}

// ---------------------------------------------------------------------------
// Attention: one CTA per (b, blk, h). Q,K,V 128x128 (hi/lo bf16) in smem.
// 8 warps; warp w owns query rows [16w, 16w+16): full rows in one warp.
// ---------------------------------------------------------------------------
__device__ __forceinline__ void attn_load(__nv_bfloat16* dst,
                                          const __nv_bfloat16* __restrict__ ghi,
                                          const __nv_bfloat16* __restrict__ glo,
                                          size_t t0, int colb, int tid) {
#pragma unroll
    for (int i = 0; i < 16; i++) {
        int cidx  = tid + i * 256;
        int plane = cidx >> 11;
        int rem   = cidx & 2047;
        int r     = rem >> 4;
        int ch    = rem & 15;
        const __nv_bfloat16* g = (plane ? glo : ghi) + (t0 + r) * (size_t)N_QKV + colb + ch * 8;
        __nv_bfloat16* s = dst + (plane * 128 + r) * 128 + (ch ^ (r & 7)) * 8;
        cp16(s, g);
    }
}

__global__ void __launch_bounds__(256, 1) attn_kernel(
    const __nv_bfloat16* __restrict__ qkv_hi, const __nv_bfloat16* __restrict__ qkv_lo,
    __nv_bfloat16* __restrict__ att_hi, __nv_bfloat16* __restrict__ att_lo)
{
    extern __shared__ __nv_bfloat16 smem[];
    __nv_bfloat16* sQ = smem;           // [2][128][128]
    __nv_bfloat16* sK = smem + 32768;
    __nv_bfloat16* sV = smem + 65536;

    const int tid  = threadIdx.x;
    const int lane = tid & 31;
    const int wid  = tid >> 5;

    const int cta = blockIdx.x;
    const int h   = cta & 15;
    const int blk = (cta >> 4) & 63;
    const int b   = cta >> 10;
    const size_t t0 = (size_t)b * TSEQ + (size_t)blk * 128;

    attn_load(sQ, qkv_hi, qkv_lo, t0, h * DHEAD, tid);
    attn_load(sK, qkv_hi, qkv_lo, t0, CDIM + h * DHEAD, tid);
    cp_commit();
    attn_load(sV, qkv_hi, qkv_lo, t0, 2 * CDIM + h * DHEAD, tid);
    cp_commit();

    cp_wait<1>();   // Q, K ready
    __syncthreads();

    // ----- scores S = Q K^T (warp tile 16 x 128), split-bf16 -----
    float s[16][4];
#pragma unroll
    for (int nt = 0; nt < 16; nt++)
#pragma unroll
        for (int e = 0; e < 4; e++) s[nt][e] = 0.f;

    const int rw0 = wid * 16;
#pragma unroll
    for (int kk = 0; kk < 8; kk++) {
        uint32_t qH[4], qL[4];
        {
            int r  = rw0 + (lane & 15);
            int ch = kk * 2 + (lane >> 4);
            int sw = ch ^ (r & 7);
            ldsm4(qH, sQ + r * 128 + sw * 8);
            ldsm4(qL, sQ + (128 + r) * 128 + sw * 8);
        }
#pragma unroll
        for (int nt = 0; nt < 16; nt++) {
            uint32_t kH[2], kL[2];
            int l16  = lane & 15;
            int nrow = nt * 8 + (l16 & 7);
            int ch   = kk * 2 + (l16 >> 3);
            int sw   = ch ^ (nrow & 7);
            ldsm2(kH, sK + nrow * 128 + sw * 8);
            ldsm2(kL, sK + (128 + nrow) * 128 + sw * 8);
            mma16816(s[nt], qH, kH);
            mma16816(s[nt], qH, kL);
            mma16816(s[nt], qL, kH);
        }
    }

    // ----- causal softmax (rows fully inside warp quads) -----
    const float scale = 0.08838834764831845f;  // 1/sqrt(128)
    const int g  = lane >> 2;
    const int tq = lane & 3;
    const int r0 = rw0 + g;
    const int r1 = r0 + 8;

    float mx0 = -1e30f, mx1 = -1e30f;
#pragma unroll
    for (int nt = 0; nt < 16; nt++) {
        int j0 = nt * 8 + tq * 2;
        int j1 = j0 + 1;
        float v;
        v = s[nt][0] * scale; if (j0 > r0) v = -1e30f; s[nt][0] = v; mx0 = fmaxf(mx0, v);
        v = s[nt][1] * scale; if (j1 > r0) v = -1e30f; s[nt][1] = v; mx0 = fmaxf(mx0, v);
        v = s[nt][2] * scale; if (j0 > r1) v = -1e30f; s[nt][2] = v; mx1 = fmaxf(mx1, v);
        v = s[nt][3] * scale; if (j1 > r1) v = -1e30f; s[nt][3] = v; mx1 = fmaxf(mx1, v);
    }
    mx0 = fmaxf(mx0, __shfl_xor_sync(0xffffffffu, mx0, 1));
    mx0 = fmaxf(mx0, __shfl_xor_sync(0xffffffffu, mx0, 2));
    mx1 = fmaxf(mx1, __shfl_xor_sync(0xffffffffu, mx1, 1));
    mx1 = fmaxf(mx1, __shfl_xor_sync(0xffffffffu, mx1, 2));

    float sum0 = 0.f, sum1 = 0.f;
#pragma unroll
    for (int nt = 0; nt < 16; nt++) {
        s[nt][0] = __expf(s[nt][0] - mx0); sum0 += s[nt][0];
        s[nt][1] = __expf(s[nt][1] - mx0); sum0 += s[nt][1];
        s[nt][2] = __expf(s[nt][2] - mx1); sum1 += s[nt][2];
        s[nt][3] = __expf(s[nt][3] - mx1); sum1 += s[nt][3];
    }
    sum0 += __shfl_xor_sync(0xffffffffu, sum0, 1);
    sum0 += __shfl_xor_sync(0xffffffffu, sum0, 2);
    sum1 += __shfl_xor_sync(0xffffffffu, sum1, 1);
    sum1 += __shfl_xor_sync(0xffffffffu, sum1, 2);
    const float inv0 = 1.f / sum0;
    const float inv1 = 1.f / sum1;

    cp_wait<0>();   // V ready
    __syncthreads();

    // ----- O = P V (P re-split to hi/lo bf16 from register S-frags) -----
    float o[16][4];
#pragma unroll
    for (int nt = 0; nt < 16; nt++)
#pragma unroll
        for (int e = 0; e < 4; e++) o[nt][e] = 0.f;

#pragma unroll
    for (int kk = 0; kk < 8; kk++) {
        uint32_t aH[4], aL[4];
        split2(s[2 * kk][0],     s[2 * kk][1],     aH[0], aL[0]);
        split2(s[2 * kk][2],     s[2 * kk][3],     aH[1], aL[1]);
        split2(s[2 * kk + 1][0], s[2 * kk + 1][1], aH[2], aL[2]);
        split2(s[2 * kk + 1][2], s[2 * kk + 1][3], aH[3], aL[3]);
#pragma unroll
        for (int nt = 0; nt < 16; nt++) {
            uint32_t vH[2], vL[2];
            int l16  = lane & 15;
            int krow = kk * 16 + l16;
            int sw   = nt ^ (krow & 7);
            ldsm2t(vH, sV + krow * 128 + sw * 8);
            ldsm2t(vL, sV + (128 + krow) * 128 + sw * 8);
            mma16816(o[nt], aH, vH);
            mma16816(o[nt], aH, vL);
            mma16816(o[nt], aL, vH);
        }
    }

    // ----- epilogue: write attn out as split bf16 (input to proj GEMM) -----
    const size_t tok0 = t0 + r0;
    const size_t tok1 = t0 + r1;
#pragma unroll
    for (int nt = 0; nt < 16; nt++) {
        int col = h * DHEAD + nt * 8 + tq * 2;
        float v0 = o[nt][0] * inv0, v1 = o[nt][1] * inv0;
        float v2 = o[nt][2] * inv1, v3 = o[nt][3] * inv1;
        uint32_t hpk, lpk;
        split2(v0, v1, hpk, lpk);
        *reinterpret_cast<uint32_t*>(att_hi + tok0 * CDIM + col) = hpk;
        *reinterpret_cast<uint32_t*>(att_lo + tok0 * CDIM + col) = lpk;
        split2(v2, v3, hpk, lpk);
        *reinterpret_cast<uint32_t*>(att_hi + tok1 * CDIM + col) = hpk;
        *reinterpret_cast<uint32_t*>(att_lo + tok1 * CDIM + col) = lpk;
    }
}

// ---------------------------------------------------------------------------
// Host launcher
// ---------------------------------------------------------------------------
extern "C" void kernel_launch(void* const* d_in, const int* in_sizes, int n_in,
                              void* d_out, int out_size) {
    const float* x  = (const float*)d_in[0];
    const float* wq = (const float*)d_in[1];
    const float* wp = (const float*)d_in[2];
    float* out = (float*)d_out;

    void *pXh, *pXl, *pWqh, *pWql, *pWph, *pWpl, *pQh, *pQl, *pAh, *pAl;
    cudaGetSymbolAddress(&pXh,  g_Xhi);
    cudaGetSymbolAddress(&pXl,  g_Xlo);
    cudaGetSymbolAddress(&pWqh, g_Wqh);
    cudaGetSymbolAddress(&pWql, g_Wql);
    cudaGetSymbolAddress(&pWph, g_Wph);
    cudaGetSymbolAddress(&pWpl, g_Wpl);
    cudaGetSymbolAddress(&pQh,  g_QKVh);
    cudaGetSymbolAddress(&pQl,  g_QKVl);
    cudaGetSymbolAddress(&pAh,  g_ATTh);
    cudaGetSymbolAddress(&pAl,  g_ATTl);

    cudaFuncSetAttribute((const void*)gemm_split_kernel<true>,
                         cudaFuncAttributeMaxDynamicSharedMemorySize, 65536);
    cudaFuncSetAttribute((const void*)gemm_split_kernel<false>,
                         cudaFuncAttributeMaxDynamicSharedMemorySize, 65536);
    cudaFuncSetAttribute((const void*)attn_kernel,
                         cudaFuncAttributeMaxDynamicSharedMemorySize, 196608);

    // 1) split inputs to (hi, lo) bf16
    {
        int n4 = (MROWS * CDIM) / 4;  // 16,777,216
        split_kernel<<<n4 / 256, 256>>>((const float4*)x, (uint32_t*)pXh, (uint32_t*)pXl, n4);
    }
    {
        int n4 = (CDIM * N_QKV) / 4;  // 3,145,728
        split_kernel<<<n4 / 256, 256>>>((const float4*)wq, (uint32_t*)pWqh, (uint32_t*)pWql, n4);
    }
    {
        int n4 = (CDIM * CDIM) / 4;   // 1,048,576
        split_kernel<<<n4 / 256, 256>>>((const float4*)wp, (uint32_t*)pWph, (uint32_t*)pWpl, n4);
    }

    // 2) QKV = X @ Wqkv  -> split bf16 output
    {
        dim3 grid(N_QKV / 128, MROWS / 128);  // (48, 256)
        gemm_split_kernel<true><<<grid, 256, 65536>>>(
            (const __nv_bfloat16*)pXh, (const __nv_bfloat16*)pXl,
            (const __nv_bfloat16*)pWqh, (const __nv_bfloat16*)pWql,
            (__nv_bfloat16*)pQh, (__nv_bfloat16*)pQl, nullptr,
            MROWS, N_QKV, CDIM);
    }

    // 3) blocked causal attention -> split bf16 output
    attn_kernel<<<BATCH * NBLK * NHEAD, 256, 196608>>>(
        (const __nv_bfloat16*)pQh, (const __nv_bfloat16*)pQl,
        (__nv_bfloat16*)pAh, (__nv_bfloat16*)pAl);

    // 4) Y = attn @ Wproj -> fp32 final output
    {
        dim3 grid(CDIM / 128, MROWS / 128);  // (16, 256)
        gemm_split_kernel<false><<<grid, 256, 65536>>>(
            (const __nv_bfloat16*)pAh, (const __nv_bfloat16*)pAl,
            (const __nv_bfloat16*)pWph, (const __nv_bfloat16*)pWpl,
            nullptr, nullptr, out,
            MROWS, CDIM, CDIM);
    }
}

// round 5
// speedup vs baseline: 1.7664x; 1.7664x over previous
#include <cuda_runtime.h>
#include <cuda_bf16.h>
#include <cuda_fp16.h>
#include <cstdint>
#include <cstddef>

// ---------------------------------------------------------------------------
// Problem constants
// ---------------------------------------------------------------------------
constexpr int BATCH = 4;
constexpr int TSEQ  = 8192;
constexpr int CDIM  = 2048;
constexpr int DHEAD = 128;
constexpr int NBLK  = 64;            // TSEQ / 128
constexpr int MROWS = BATCH * TSEQ;  // 32768
constexpr int N_QKV = 3 * CDIM;      // 6144
constexpr int NHEAD = 16;

// ---------------------------------------------------------------------------
// Static scratch (no allocations allowed)
// ---------------------------------------------------------------------------
__device__ __align__(256) __half g_Xh [(size_t)MROWS * CDIM];
__device__ __align__(256) __half g_Xl [(size_t)MROWS * CDIM];
__device__ __align__(256) __half g_Wq [(size_t)CDIM * N_QKV];   // [K][N] native
__device__ __align__(256) __half g_Wp [(size_t)CDIM * CDIM];    // [K][N] native
__device__ __align__(256) float  g_QKV[(size_t)MROWS * N_QKV];  // fp32 intermediates
__device__ __align__(256) __half g_Ah [(size_t)MROWS * CDIM];
__device__ __align__(256) __half g_Al [(size_t)MROWS * CDIM];

// ---------------------------------------------------------------------------
// Helpers
// ---------------------------------------------------------------------------
__device__ __forceinline__ uint32_t smem_u32(const void* p) {
    return (uint32_t)__cvta_generic_to_shared(p);
}
__device__ __forceinline__ void cp16s(uint32_t s, const void* g) {
    asm volatile("cp.async.cg.shared.global [%0], [%1], 16;" :: "r"(s), "l"(g));
}
__device__ __forceinline__ void cp_commit() {
    asm volatile("cp.async.commit_group;");
}
template <int N>
__device__ __forceinline__ void cp_wait() {
    asm volatile("cp.async.wait_group %0;" :: "n"(N));
}

__device__ __forceinline__ uint32_t pkb2(__nv_bfloat16 a, __nv_bfloat16 b) {
    __nv_bfloat162 t; t.x = a; t.y = b;
    return *reinterpret_cast<uint32_t*>(&t);
}
__device__ __forceinline__ uint32_t pkh2(__half a, __half b) {
    __half2 t; t.x = a; t.y = b;
    return *reinterpret_cast<uint32_t*>(&t);
}
// fp32 -> bf16 hi/lo split (packed pairs)
__device__ __forceinline__ void split2b(float a, float b, uint32_t& hi, uint32_t& lo) {
    __nv_bfloat16 ha = __float2bfloat16(a);
    __nv_bfloat16 hb = __float2bfloat16(b);
    __nv_bfloat16 la = __float2bfloat16(a - __bfloat162float(ha));
    __nv_bfloat16 lb = __float2bfloat16(b - __bfloat162float(hb));
    hi = pkb2(ha, hb);
    lo = pkb2(la, lb);
}
// fp32 -> fp16 hi/lo split (packed pairs)
__device__ __forceinline__ void split2h(float a, float b, uint32_t& hi, uint32_t& lo) {
    __half ha = __float2half_rn(a);
    __half hb = __float2half_rn(b);
    __half la = __float2half_rn(a - __half2float(ha));
    __half lb = __float2half_rn(b - __half2float(hb));
    hi = pkh2(ha, hb);
    lo = pkh2(la, lb);
}

__device__ __forceinline__ void ldsm4a(uint32_t* d, uint32_t a) {
    asm volatile("ldmatrix.sync.aligned.m8n8.x4.shared.b16 {%0,%1,%2,%3}, [%4];"
                 : "=r"(d[0]), "=r"(d[1]), "=r"(d[2]), "=r"(d[3]) : "r"(a));
}
__device__ __forceinline__ void ldsm2a(uint32_t* d, uint32_t a) {
    asm volatile("ldmatrix.sync.aligned.m8n8.x2.shared.b16 {%0,%1}, [%2];"
                 : "=r"(d[0]), "=r"(d[1]) : "r"(a));
}
__device__ __forceinline__ void ldsm2ta(uint32_t* d, uint32_t a) {
    asm volatile("ldmatrix.sync.aligned.m8n8.x2.trans.shared.b16 {%0,%1}, [%2];"
                 : "=r"(d[0]), "=r"(d[1]) : "r"(a));
}
// bf16 mma (attention)
__device__ __forceinline__ void mma_bf(float* c, const uint32_t* a, const uint32_t* b) {
    asm volatile(
        "mma.sync.aligned.m16n8k16.row.col.f32.bf16.bf16.f32 "
        "{%0,%1,%2,%3}, {%4,%5,%6,%7}, {%8,%9}, {%0,%1,%2,%3};"
        : "+f"(c[0]), "+f"(c[1]), "+f"(c[2]), "+f"(c[3])
        : "r"(a[0]), "r"(a[1]), "r"(a[2]), "r"(a[3]), "r"(b[0]), "r"(b[1]));
}
// fp16 mma (GEMMs)
__device__ __forceinline__ void mma_h(float* c, const uint32_t* a, const uint32_t* b) {
    asm volatile(
        "mma.sync.aligned.m16n8k16.row.col.f32.f16.f16.f32 "
        "{%0,%1,%2,%3}, {%4,%5,%6,%7}, {%8,%9}, {%0,%1,%2,%3};"
        : "+f"(c[0]), "+f"(c[1]), "+f"(c[2]), "+f"(c[3])
        : "r"(a[0]), "r"(a[1]), "r"(a[2]), "r"(a[3]), "r"(b[0]), "r"(b[1]));
}

// ---------------------------------------------------------------------------
// fp32 -> fp16 (hi, lo) split
// ---------------------------------------------------------------------------
__global__ void split_h_kernel(const float4* __restrict__ src,
                               uint32_t* __restrict__ hi,
                               uint32_t* __restrict__ lo, int n4) {
    int i = blockIdx.x * blockDim.x + threadIdx.x;
    if (i >= n4) return;
    float4 v = src[i];
    uint32_t h0, l0, h1, l1;
    split2h(v.x, v.y, h0, l0);
    split2h(v.z, v.w, h1, l1);
    hi[2 * i] = h0;  hi[2 * i + 1] = h1;
    lo[2 * i] = l0;  lo[2 * i + 1] = l1;
}
// fp32 -> fp16 (single, RN)
__global__ void cvt_h_kernel(const float4* __restrict__ src,
                             uint32_t* __restrict__ dst, int n4) {
    int i = blockIdx.x * blockDim.x + threadIdx.x;
    if (i >= n4) return;
    float4 v = src[i];
    dst[2 * i]     = pkh2(__float2half_rn(v.x), __float2half_rn(v.y));
    dst[2 * i + 1] = pkh2(__float2half_rn(v.z), __float2half_rn(v.w));
}

// ---------------------------------------------------------------------------
// fp16 2-pass split-A GEMM: C[M,N] = (Ah + Al)[M,K] @ B[K,N], fp32 out
// BM=128, BN=128, BK=32, 4-stage cp.async ring, 256 threads (8 warps, 2x4),
// warp tile 64x32, 2 CTAs/SM.
// Stage layout (24576 B): A plane0 @0 (8KB), A plane1 @8192, B @16384 (8KB).
// ---------------------------------------------------------------------------
constexpr int G_STAGE = 24576;
constexpr int G_SMEM  = 4 * G_STAGE;  // 98304

__global__ void __launch_bounds__(256, 2) gemm_fp16_2p(
    const __half* __restrict__ Ah, const __half* __restrict__ Al,
    const __half* __restrict__ B,  float* __restrict__ C,
    int Nn, int Kk)
{
    extern __shared__ char smem[];
    const uint32_t sbase = smem_u32(smem);
    const int tid  = threadIdx.x;
    const int lane = tid & 31;
    const int wid  = tid >> 5;
    const int m0   = blockIdx.y * 128;
    const int n0   = blockIdx.x * 128;
    const int wm   = (wid >> 2) * 64;
    const int wn   = (wid & 3) * 32;

    // per-thread load slots: 4 A chunks + 2 B chunks of 16B
    const char* gA[4]; uint32_t sA[4];
#pragma unroll
    for (int i = 0; i < 4; i++) {
        int idx = tid + i * 256;
        int plane = idx >> 9;
        int rem = idx & 511;
        int r = rem >> 2, ch = rem & 3;
        const __half* base = plane ? Al : Ah;
        gA[i] = (const char*)(base + (size_t)(m0 + r) * Kk + ch * 8);
        sA[i] = sbase + plane * 8192 + r * 64 + ((ch ^ ((r >> 1) & 3)) * 16);
    }
    const char* gB[2]; uint32_t sB[2];
#pragma unroll
    for (int i = 0; i < 2; i++) {
        int idx = tid + i * 256;
        int r = idx >> 4, ch = idx & 15;
        gB[i] = (const char*)(B + (size_t)r * Nn + n0 + ch * 8);
        sB[i] = sbase + 16384 + r * 256 + ((ch ^ (r & 7)) * 16);
    }
    const size_t stepA = 64;                 // 32 halfs
    const size_t stepB = (size_t)32 * Nn * 2;

    const int NK = Kk / 32;

    // prologue: stages 0..2
#pragma unroll
    for (int s = 0; s < 3; s++) {
        uint32_t so = (uint32_t)(s * G_STAGE);
#pragma unroll
        for (int i = 0; i < 4; i++) cp16s(sA[i] + so, gA[i] + (size_t)s * stepA);
#pragma unroll
        for (int i = 0; i < 2; i++) cp16s(sB[i] + so, gB[i] + (size_t)s * stepB);
        cp_commit();
    }

    float c[4][4][4];
#pragma unroll
    for (int mt = 0; mt < 4; mt++)
#pragma unroll
        for (int nt = 0; nt < 4; nt++)
#pragma unroll
            for (int e = 0; e < 4; e++) c[mt][nt][e] = 0.f;

    for (int kt = 0; kt < NK; kt++) {
        cp_wait<2>();
        __syncthreads();
        const uint32_t sbuf = sbase + (kt & 3) * G_STAGE;

#pragma unroll
        for (int kk = 0; kk < 2; kk++) {
            uint32_t b[4][2];
#pragma unroll
            for (int nt = 0; nt < 4; nt++) {
                int l16  = lane & 15;
                int krow = kk * 16 + l16;
                int ch   = (wn >> 3) + nt;
                int sw   = ch ^ (krow & 7);
                ldsm2ta(b[nt], sbuf + 16384 + krow * 256 + sw * 16);
            }
#pragma unroll
            for (int mt = 0; mt < 4; mt++) {
                int r  = wm + mt * 16 + (lane & 15);
                int ch = kk * 2 + (lane >> 4);
                int sw = ch ^ ((r >> 1) & 3);
                uint32_t aH[4], aL[4];
                ldsm4a(aH, sbuf + r * 64 + sw * 16);
                ldsm4a(aL, sbuf + 8192 + r * 64 + sw * 16);
#pragma unroll
                for (int nt = 0; nt < 4; nt++) {
                    mma_h(c[mt][nt], aH, b[nt]);
                    mma_h(c[mt][nt], aL, b[nt]);
                }
            }
        }

        int kn = kt + 3;
        if (kn < NK) {
            uint32_t so = (uint32_t)((kn & 3) * G_STAGE);
#pragma unroll
            for (int i = 0; i < 4; i++) cp16s(sA[i] + so, gA[i] + (size_t)kn * stepA);
#pragma unroll
            for (int i = 0; i < 2; i++) cp16s(sB[i] + so, gB[i] + (size_t)kn * stepB);
        }
        cp_commit();
    }

    // epilogue: fp32
#pragma unroll
    for (int mt = 0; mt < 4; mt++) {
#pragma unroll
        for (int nt = 0; nt < 4; nt++) {
            int row = m0 + wm + mt * 16 + (lane >> 2);
            int col = n0 + wn + nt * 8 + (lane & 3) * 2;
            *reinterpret_cast<float2*>(C + (size_t)row * Nn + col) =
                make_float2(c[mt][nt][0], c[mt][nt][1]);
            *reinterpret_cast<float2*>(C + (size_t)(row + 8) * Nn + col) =
                make_float2(c[mt][nt][2], c[mt][nt][3]);
        }
    }
}

// ---------------------------------------------------------------------------
// Attention: one CTA per (b, blk, h). fp32 QKV in, split-bf16 3-pass math,
// fp16-pair out. smem: sQ/sK/sV each [2 planes][128][128] bf16 = 64KB -> 192KB
// ---------------------------------------------------------------------------
__device__ __forceinline__ void attn_cvt(__nv_bfloat16* dst,
                                         const float* __restrict__ qkv,
                                         size_t t0, int colb, int tid) {
#pragma unroll
    for (int i = 0; i < 8; i++) {
        int idx = tid + i * 256;     // 2048 chunk tasks: 128 rows x 16 chunks
        int r  = idx >> 4;
        int ch = idx & 15;
        const float4* g = reinterpret_cast<const float4*>(
            qkv + (t0 + r) * (size_t)N_QKV + colb + ch * 8);
        float4 u0 = g[0];
        float4 u1 = g[1];
        uint32_t hi[4], lo[4];
        split2b(u0.x, u0.y, hi[0], lo[0]);
        split2b(u0.z, u0.w, hi[1], lo[1]);
        split2b(u1.x, u1.y, hi[2], lo[2]);
        split2b(u1.z, u1.w, hi[3], lo[3]);
        int sw = (ch ^ (r & 7)) * 8;
        *reinterpret_cast<uint4*>(dst + r * 128 + sw) =
            *reinterpret_cast<uint4*>(hi);
        *reinterpret_cast<uint4*>(dst + (128 + r) * 128 + sw) =
            *reinterpret_cast<uint4*>(lo);
    }
}

__global__ void __launch_bounds__(256, 1) attn_kernel(
    const float* __restrict__ qkv,
    __half* __restrict__ att_hi, __half* __restrict__ att_lo)
{
    extern __shared__ char smem[];
    __nv_bfloat16* sQ = reinterpret_cast<__nv_bfloat16*>(smem);
    __nv_bfloat16* sK = reinterpret_cast<__nv_bfloat16*>(smem) + 32768;
    __nv_bfloat16* sV = reinterpret_cast<__nv_bfloat16*>(smem) + 65536;

    const int tid  = threadIdx.x;
    const int lane = tid & 31;
    const int wid  = tid >> 5;

    const int cta = blockIdx.x;
    const int h   = cta & 15;
    const int blk = (cta >> 4) & 63;
    const int b   = cta >> 10;
    const size_t t0 = (size_t)b * TSEQ + (size_t)blk * 128;

    attn_cvt(sQ, qkv, t0, h * DHEAD, tid);
    attn_cvt(sK, qkv, t0, CDIM + h * DHEAD, tid);
    attn_cvt(sV, qkv, t0, 2 * CDIM + h * DHEAD, tid);
    __syncthreads();

    // ----- S = Q K^T (warp tile 16 x 128), split-bf16 3-pass -----
    float s[16][4];
#pragma unroll
    for (int nt = 0; nt < 16; nt++)
#pragma unroll
        for (int e = 0; e < 4; e++) s[nt][e] = 0.f;

    const int rw0 = wid * 16;
#pragma unroll
    for (int kk = 0; kk < 8; kk++) {
        uint32_t qH[4], qL[4];
        {
            int r  = rw0 + (lane & 15);
            int ch = kk * 2 + (lane >> 4);
            int sw = ch ^ (r & 7);
            ldsm4a(qH, smem_u32(sQ + r * 128 + sw * 8));
            ldsm4a(qL, smem_u32(sQ + (128 + r) * 128 + sw * 8));
        }
#pragma unroll
        for (int nt = 0; nt < 16; nt++) {
            uint32_t kH[2], kL[2];
            int l16  = lane & 15;
            int nrow = nt * 8 + (l16 & 7);
            int ch   = kk * 2 + (l16 >> 3);
            int sw   = ch ^ (nrow & 7);
            ldsm2a(kH, smem_u32(sK + nrow * 128 + sw * 8));
            ldsm2a(kL, smem_u32(sK + (128 + nrow) * 128 + sw * 8));
            mma_bf(s[nt], qH, kH);
            mma_bf(s[nt], qH, kL);
            mma_bf(s[nt], qL, kH);
        }
    }

    // ----- causal softmax -----
    const float scale = 0.08838834764831845f;  // 1/sqrt(128)
    const int g  = lane >> 2;
    const int tq = lane & 3;
    const int r0 = rw0 + g;
    const int r1 = r0 + 8;

    float mx0 = -1e30f, mx1 = -1e30f;
#pragma unroll
    for (int nt = 0; nt < 16; nt++) {
        int j0 = nt * 8 + tq * 2;
        int j1 = j0 + 1;
        float v;
        v = s[nt][0] * scale; if (j0 > r0) v = -1e30f; s[nt][0] = v; mx0 = fmaxf(mx0, v);
        v = s[nt][1] * scale; if (j1 > r0) v = -1e30f; s[nt][1] = v; mx0 = fmaxf(mx0, v);
        v = s[nt][2] * scale; if (j0 > r1) v = -1e30f; s[nt][2] = v; mx1 = fmaxf(mx1, v);
        v = s[nt][3] * scale; if (j1 > r1) v = -1e30f; s[nt][3] = v; mx1 = fmaxf(mx1, v);
    }
    mx0 = fmaxf(mx0, __shfl_xor_sync(0xffffffffu, mx0, 1));
    mx0 = fmaxf(mx0, __shfl_xor_sync(0xffffffffu, mx0, 2));
    mx1 = fmaxf(mx1, __shfl_xor_sync(0xffffffffu, mx1, 1));
    mx1 = fmaxf(mx1, __shfl_xor_sync(0xffffffffu, mx1, 2));

    float sum0 = 0.f, sum1 = 0.f;
#pragma unroll
    for (int nt = 0; nt < 16; nt++) {
        s[nt][0] = __expf(s[nt][0] - mx0); sum0 += s[nt][0];
        s[nt][1] = __expf(s[nt][1] - mx0); sum0 += s[nt][1];
        s[nt][2] = __expf(s[nt][2] - mx1); sum1 += s[nt][2];
        s[nt][3] = __expf(s[nt][3] - mx1); sum1 += s[nt][3];
    }
    sum0 += __shfl_xor_sync(0xffffffffu, sum0, 1);
    sum0 += __shfl_xor_sync(0xffffffffu, sum0, 2);
    sum1 += __shfl_xor_sync(0xffffffffu, sum1, 1);
    sum1 += __shfl_xor_sync(0xffffffffu, sum1, 2);
    const float inv0 = 1.f / sum0;
    const float inv1 = 1.f / sum1;

    // ----- O = P V (P split to bf16 hi/lo in regs), 3-pass -----
    float o[16][4];
#pragma unroll
    for (int nt = 0; nt < 16; nt++)
#pragma unroll
        for (int e = 0; e < 4; e++) o[nt][e] = 0.f;

#pragma unroll
    for (int kk = 0; kk < 8; kk++) {
        uint32_t aH[4], aL[4];
        split2b(s[2 * kk][0],     s[2 * kk][1],     aH[0], aL[0]);
        split2b(s[2 * kk][2],     s[2 * kk][3],     aH[1], aL[1]);
        split2b(s[2 * kk + 1][0], s[2 * kk + 1][1], aH[2], aL[2]);
        split2b(s[2 * kk + 1][2], s[2 * kk + 1][3], aH[3], aL[3]);
#pragma unroll
        for (int nt = 0; nt < 16; nt++) {
            uint32_t vH[2], vL[2];
            int l16  = lane & 15;
            int krow = kk * 16 + l16;
            int sw   = nt ^ (krow & 7);
            ldsm2ta(vH, smem_u32(sV + krow * 128 + sw * 8));
            ldsm2ta(vL, smem_u32(sV + (128 + krow) * 128 + sw * 8));
            mma_bf(o[nt], aH, vH);
            mma_bf(o[nt], aH, vL);
            mma_bf(o[nt], aL, vH);
        }
    }

    // ----- epilogue: fp16 pair (input to proj GEMM) -----
    const size_t tok0 = t0 + r0;
    const size_t tok1 = t0 + r1;
#pragma unroll
    for (int nt = 0; nt < 16; nt++) {
        int col = h * DHEAD + nt * 8 + tq * 2;
        float v0 = o[nt][0] * inv0, v1 = o[nt][1] * inv0;
        float v2 = o[nt][2] * inv1, v3 = o[nt][3] * inv1;
        uint32_t hpk, lpk;
        split2h(v0, v1, hpk, lpk);
        *reinterpret_cast<uint32_t*>(att_hi + tok0 * CDIM + col) = hpk;
        *reinterpret_cast<uint32_t*>(att_lo + tok0 * CDIM + col) = lpk;
        split2h(v2, v3, hpk, lpk);
        *reinterpret_cast<uint32_t*>(att_hi + tok1 * CDIM + col) = hpk;
        *reinterpret_cast<uint32_t*>(att_lo + tok1 * CDIM + col) = lpk;
    }
}

// ---------------------------------------------------------------------------
// Host launcher
// ---------------------------------------------------------------------------
extern "C" void kernel_launch(void* const* d_in, const int* in_sizes, int n_in,
                              void* d_out, int out_size) {
    const float* x  = (const float*)d_in[0];
    const float* wq = (const float*)d_in[1];
    const float* wp = (const float*)d_in[2];
    float* out = (float*)d_out;

    void *pXh, *pXl, *pWq, *pWp, *pQKV, *pAh, *pAl;
    cudaGetSymbolAddress(&pXh,  g_Xh);
    cudaGetSymbolAddress(&pXl,  g_Xl);
    cudaGetSymbolAddress(&pWq,  g_Wq);
    cudaGetSymbolAddress(&pWp,  g_Wp);
    cudaGetSymbolAddress(&pQKV, g_QKV);
    cudaGetSymbolAddress(&pAh,  g_Ah);
    cudaGetSymbolAddress(&pAl,  g_Al);

    cudaFuncSetAttribute((const void*)gemm_fp16_2p,
                         cudaFuncAttributeMaxDynamicSharedMemorySize, G_SMEM);
    cudaFuncSetAttribute((const void*)attn_kernel,
                         cudaFuncAttributeMaxDynamicSharedMemorySize, 196608);

    // 1) X -> fp16 pair; W -> fp16
    {
        int n4 = (MROWS * CDIM) / 4;
        split_h_kernel<<<n4 / 256, 256>>>((const float4*)x,
                                          (uint32_t*)pXh, (uint32_t*)pXl, n4);
    }
    {
        int n4 = (CDIM * N_QKV) / 4;
        cvt_h_kernel<<<n4 / 256, 256>>>((const float4*)wq, (uint32_t*)pWq, n4);
    }
    {
        int n4 = (CDIM * CDIM) / 4;
        cvt_h_kernel<<<n4 / 256, 256>>>((const float4*)wp, (uint32_t*)pWp, n4);
    }

    // 2) QKV = (Xh+Xl) @ Wq  -> fp32
    {
        dim3 grid(N_QKV / 128, MROWS / 128);  // (48, 256)
        gemm_fp16_2p<<<grid, 256, G_SMEM>>>(
            (const __half*)pXh, (const __half*)pXl, (const __half*)pWq,
            (float*)pQKV, N_QKV, CDIM);
    }

    // 3) blocked causal attention -> fp16 pair
    attn_kernel<<<BATCH * NBLK * NHEAD, 256, 196608>>>(
        (const float*)pQKV, (__half*)pAh, (__half*)pAl);

    // 4) Y = (Ah+Al) @ Wp -> fp32 final output
    {
        dim3 grid(CDIM / 128, MROWS / 128);   // (16, 256)
        gemm_fp16_2p<<<grid, 256, G_SMEM>>>(
            (const __half*)pAh, (const __half*)pAl, (const __half*)pWp,
            out, CDIM, CDIM);
    }
}

// round 7
// speedup vs baseline: 2.8817x; 1.6314x over previous
#include <cuda_runtime.h>
#include <cuda_bf16.h>
#include <cuda_fp16.h>
#include <cstdint>
#include <cstddef>

// ---------------------------------------------------------------------------
// Problem constants
// ---------------------------------------------------------------------------
constexpr int BATCH = 4;
constexpr int TSEQ  = 8192;
constexpr int CDIM  = 2048;
constexpr int DHEAD = 128;
constexpr int NBLK  = 64;            // TSEQ / 128
constexpr int MROWS = BATCH * TSEQ;  // 32768
constexpr int N_QKV = 3 * CDIM;      // 6144
constexpr int NHEAD = 16;

// ---------------------------------------------------------------------------
// Static scratch (no allocations allowed)
// ---------------------------------------------------------------------------
__device__ __align__(256) __half g_X  [(size_t)MROWS * CDIM];
__device__ __align__(256) __half g_Wq [(size_t)CDIM * N_QKV];   // [K][N] native
__device__ __align__(256) __half g_Wp [(size_t)CDIM * CDIM];    // [K][N] native
__device__ __align__(256) float  g_QKV[(size_t)MROWS * N_QKV];  // fp32 intermediates
__device__ __align__(256) __half g_A  [(size_t)MROWS * CDIM];

// ---------------------------------------------------------------------------
// Helpers
// ---------------------------------------------------------------------------
__device__ __forceinline__ uint32_t smem_u32(const void* p) {
    return (uint32_t)__cvta_generic_to_shared(p);
}
__device__ __forceinline__ void cp16s(uint32_t s, const void* g) {
    asm volatile("cp.async.cg.shared.global [%0], [%1], 16;" :: "r"(s), "l"(g));
}
__device__ __forceinline__ void cp_commit() {
    asm volatile("cp.async.commit_group;");
}
template <int N>
__device__ __forceinline__ void cp_wait() {
    asm volatile("cp.async.wait_group %0;" :: "n"(N));
}

__device__ __forceinline__ uint32_t pkb2(__nv_bfloat16 a, __nv_bfloat16 b) {
    __nv_bfloat162 t; t.x = a; t.y = b;
    return *reinterpret_cast<uint32_t*>(&t);
}
__device__ __forceinline__ uint32_t pkh2(__half a, __half b) {
    __half2 t; t.x = a; t.y = b;
    return *reinterpret_cast<uint32_t*>(&t);
}
// fp32 -> bf16 hi/lo split (packed pairs)
__device__ __forceinline__ void split2b(float a, float b, uint32_t& hi, uint32_t& lo) {
    __nv_bfloat16 ha = __float2bfloat16(a);
    __nv_bfloat16 hb = __float2bfloat16(b);
    __nv_bfloat16 la = __float2bfloat16(a - __bfloat162float(ha));
    __nv_bfloat16 lb = __float2bfloat16(b - __bfloat162float(hb));
    hi = pkb2(ha, hb);
    lo = pkb2(la, lb);
}

__device__ __forceinline__ void ldsm4a(uint32_t* d, uint32_t a) {
    asm volatile("ldmatrix.sync.aligned.m8n8.x4.shared.b16 {%0,%1,%2,%3}, [%4];"
                 : "=r"(d[0]), "=r"(d[1]), "=r"(d[2]), "=r"(d[3]) : "r"(a));
}
__device__ __forceinline__ void ldsm2a(uint32_t* d, uint32_t a) {
    asm volatile("ldmatrix.sync.aligned.m8n8.x2.shared.b16 {%0,%1}, [%2];"
                 : "=r"(d[0]), "=r"(d[1]) : "r"(a));
}
__device__ __forceinline__ void ldsm2ta(uint32_t* d, uint32_t a) {
    asm volatile("ldmatrix.sync.aligned.m8n8.x2.trans.shared.b16 {%0,%1}, [%2];"
                 : "=r"(d[0]), "=r"(d[1]) : "r"(a));
}
// bf16 mma (attention)
__device__ __forceinline__ void mma_bf(float* c, const uint32_t* a, const uint32_t* b) {
    asm volatile(
        "mma.sync.aligned.m16n8k16.row.col.f32.bf16.bf16.f32 "
        "{%0,%1,%2,%3}, {%4,%5,%6,%7}, {%8,%9}, {%0,%1,%2,%3};"
        : "+f"(c[0]), "+f"(c[1]), "+f"(c[2]), "+f"(c[3])
        : "r"(a[0]), "r"(a[1]), "r"(a[2]), "r"(a[3]), "r"(b[0]), "r"(b[1]));
}
// fp16 mma (GEMMs)
__device__ __forceinline__ void mma_h(float* c, const uint32_t* a, const uint32_t* b) {
    asm volatile(
        "mma.sync.aligned.m16n8k16.row.col.f32.f16.f16.f32 "
        "{%0,%1,%2,%3}, {%4,%5,%6,%7}, {%8,%9}, {%0,%1,%2,%3};"
        : "+f"(c[0]), "+f"(c[1]), "+f"(c[2]), "+f"(c[3])
        : "r"(a[0]), "r"(a[1]), "r"(a[2]), "r"(a[3]), "r"(b[0]), "r"(b[1]));
}

// ---------------------------------------------------------------------------
// fp32 -> fp16 (single, RN)
// ---------------------------------------------------------------------------
__global__ void cvt_h_kernel(const float4* __restrict__ src,
                             uint32_t* __restrict__ dst, int n4) {
    int i = blockIdx.x * blockDim.x + threadIdx.x;
    if (i >= n4) return;
    float4 v = src[i];
    dst[2 * i]     = pkh2(__float2half_rn(v.x), __float2half_rn(v.y));
    dst[2 * i + 1] = pkh2(__float2half_rn(v.z), __float2half_rn(v.w));
}

// ---------------------------------------------------------------------------
// fp16 single-pass GEMM: C[M,N] = A[M,K] @ B[K,N], fp32 out
// BM=128, BN=128, BK=32, 4-stage cp.async ring, 256 threads (8 warps, 2x4),
// warp tile 64x32, 2 CTAs/SM.
// Stage layout (16384 B): A @0 (8KB), B @8192 (8KB).
// ---------------------------------------------------------------------------
constexpr int G_STAGE = 16384;
constexpr int G_SMEM  = 4 * G_STAGE;  // 65536

__global__ void __launch_bounds__(256, 2) gemm_fp16(
    const __half* __restrict__ A, const __half* __restrict__ B,
    float* __restrict__ C, int Nn, int Kk)
{
    extern __shared__ char smem[];
    const uint32_t sbase = smem_u32(smem);
    const int tid  = threadIdx.x;
    const int lane = tid & 31;
    const int wid  = tid >> 5;
    const int m0   = blockIdx.y * 128;
    const int n0   = blockIdx.x * 128;
    const int wm   = (wid >> 2) * 64;
    const int wn   = (wid & 3) * 32;

    // per-thread load slots: 2 A chunks + 2 B chunks of 16B
    const char* gA[2]; uint32_t sA[2];
#pragma unroll
    for (int i = 0; i < 2; i++) {
        int idx = tid + i * 256;
        int r = idx >> 2, ch = idx & 3;
        gA[i] = (const char*)(A + (size_t)(m0 + r) * Kk + ch * 8);
        sA[i] = sbase + r * 64 + ((ch ^ ((r >> 1) & 3)) * 16);
    }
    const char* gB[2]; uint32_t sB[2];
#pragma unroll
    for (int i = 0; i < 2; i++) {
        int idx = tid + i * 256;
        int r = idx >> 4, ch = idx & 15;
        gB[i] = (const char*)(B + (size_t)r * Nn + n0 + ch * 8);
        sB[i] = sbase + 8192 + r * 256 + ((ch ^ (r & 7)) * 16);
    }
    const size_t stepA = 64;                 // 32 halfs
    const size_t stepB = (size_t)32 * Nn * 2;

    const int NK = Kk / 32;

    // prologue: stages 0..2
#pragma unroll
    for (int s = 0; s < 3; s++) {
        uint32_t so = (uint32_t)(s * G_STAGE);
#pragma unroll
        for (int i = 0; i < 2; i++) cp16s(sA[i] + so, gA[i] + (size_t)s * stepA);
#pragma unroll
        for (int i = 0; i < 2; i++) cp16s(sB[i] + so, gB[i] + (size_t)s * stepB);
        cp_commit();
    }

    float c[4][4][4];
#pragma unroll
    for (int mt = 0; mt < 4; mt++)
#pragma unroll
        for (int nt = 0; nt < 4; nt++)
#pragma unroll
            for (int e = 0; e < 4; e++) c[mt][nt][e] = 0.f;

    for (int kt = 0; kt < NK; kt++) {
        cp_wait<2>();
        __syncthreads();
        const uint32_t sbuf = sbase + (kt & 3) * G_STAGE;

#pragma unroll
        for (int kk = 0; kk < 2; kk++) {
            uint32_t b[4][2];
#pragma unroll
            for (int nt = 0; nt < 4; nt++) {
                int l16  = lane & 15;
                int krow = kk * 16 + l16;
                int ch   = (wn >> 3) + nt;
                int sw   = ch ^ (krow & 7);
                ldsm2ta(b[nt], sbuf + 8192 + krow * 256 + sw * 16);
            }
#pragma unroll
            for (int mt = 0; mt < 4; mt++) {
                int r  = wm + mt * 16 + (lane & 15);
                int ch = kk * 2 + (lane >> 4);
                int sw = ch ^ ((r >> 1) & 3);
                uint32_t a[4];
                ldsm4a(a, sbuf + r * 64 + sw * 16);
#pragma unroll
                for (int nt = 0; nt < 4; nt++)
                    mma_h(c[mt][nt], a, b[nt]);
            }
        }

        int kn = kt + 3;
        if (kn < NK) {
            uint32_t so = (uint32_t)((kn & 3) * G_STAGE);
#pragma unroll
            for (int i = 0; i < 2; i++) cp16s(sA[i] + so, gA[i] + (size_t)kn * stepA);
#pragma unroll
            for (int i = 0; i < 2; i++) cp16s(sB[i] + so, gB[i] + (size_t)kn * stepB);
        }
        cp_commit();
    }

    // epilogue: fp32
#pragma unroll
    for (int mt = 0; mt < 4; mt++) {
#pragma unroll
        for (int nt = 0; nt < 4; nt++) {
            int row = m0 + wm + mt * 16 + (lane >> 2);
            int col = n0 + wn + nt * 8 + (lane & 3) * 2;
            *reinterpret_cast<float2*>(C + (size_t)row * Nn + col) =
                make_float2(c[mt][nt][0], c[mt][nt][1]);
            *reinterpret_cast<float2*>(C + (size_t)(row + 8) * Nn + col) =
                make_float2(c[mt][nt][2], c[mt][nt][3]);
        }
    }
}

// ---------------------------------------------------------------------------
// Attention: one CTA per (b, blk, h). fp32 QKV in, split-bf16 3-pass math,
// fp16 out. smem: sQ/sK/sV each [2 planes][128][128] bf16 = 64KB -> 192KB
// ---------------------------------------------------------------------------
__device__ __forceinline__ void attn_cvt(__nv_bfloat16* dst,
                                         const float* __restrict__ qkv,
                                         size_t t0, int colb, int tid) {
#pragma unroll
    for (int i = 0; i < 8; i++) {
        int idx = tid + i * 256;     // 2048 chunk tasks: 128 rows x 16 chunks
        int r  = idx >> 4;
        int ch = idx & 15;
        const float4* g = reinterpret_cast<const float4*>(
            qkv + (t0 + r) * (size_t)N_QKV + colb + ch * 8);
        float4 u0 = g[0];
        float4 u1 = g[1];
        uint32_t hi[4], lo[4];
        split2b(u0.x, u0.y, hi[0], lo[0]);
        split2b(u0.z, u0.w, hi[1], lo[1]);
        split2b(u1.x, u1.y, hi[2], lo[2]);
        split2b(u1.z, u1.w, hi[3], lo[3]);
        int sw = (ch ^ (r & 7)) * 8;
        *reinterpret_cast<uint4*>(dst + r * 128 + sw) =
            *reinterpret_cast<uint4*>(hi);
        *reinterpret_cast<uint4*>(dst + (128 + r) * 128 + sw) =
            *reinterpret_cast<uint4*>(lo);
    }
}

__global__ void __launch_bounds__(256, 1) attn_kernel(
    const float* __restrict__ qkv, __half* __restrict__ att)
{
    extern __shared__ char smem[];
    __nv_bfloat16* sQ = reinterpret_cast<__nv_bfloat16*>(smem);
    __nv_bfloat16* sK = reinterpret_cast<__nv_bfloat16*>(smem) + 32768;
    __nv_bfloat16* sV = reinterpret_cast<__nv_bfloat16*>(smem) + 65536;

    const int tid  = threadIdx.x;
    const int lane = tid & 31;
    const int wid  = tid >> 5;

    const int cta = blockIdx.x;
    const int h   = cta & 15;
    const int blk = (cta >> 4) & 63;
    const int b   = cta >> 10;
    const size_t t0 = (size_t)b * TSEQ + (size_t)blk * 128;

    attn_cvt(sQ, qkv, t0, h * DHEAD, tid);
    attn_cvt(sK, qkv, t0, CDIM + h * DHEAD, tid);
    attn_cvt(sV, qkv, t0, 2 * CDIM + h * DHEAD, tid);
    __syncthreads();

    // ----- S = Q K^T (warp tile 16 x 128), split-bf16 3-pass -----
    float s[16][4];
#pragma unroll
    for (int nt = 0; nt < 16; nt++)
#pragma unroll
        for (int e = 0; e < 4; e++) s[nt][e] = 0.f;

    const int rw0 = wid * 16;
#pragma unroll
    for (int kk = 0; kk < 8; kk++) {
        uint32_t qH[4], qL[4];
        {
            int r  = rw0 + (lane & 15);
            int ch = kk * 2 + (lane >> 4);
            int sw = ch ^ (r & 7);
            ldsm4a(qH, smem_u32(sQ + r * 128 + sw * 8));
            ldsm4a(qL, smem_u32(sQ + (128 + r) * 128 + sw * 8));
        }
#pragma unroll
        for (int nt = 0; nt < 16; nt++) {
            uint32_t kH[2], kL[2];
            int l16  = lane & 15;
            int nrow = nt * 8 + (l16 & 7);
            int ch   = kk * 2 + (l16 >> 3);
            int sw   = ch ^ (nrow & 7);
            ldsm2a(kH, smem_u32(sK + nrow * 128 + sw * 8));
            ldsm2a(kL, smem_u32(sK + (128 + nrow) * 128 + sw * 8));
            mma_bf(s[nt], qH, kH);
            mma_bf(s[nt], qH, kL);
            mma_bf(s[nt], qL, kH);
        }
    }

    // ----- causal softmax -----
    const float scale = 0.08838834764831845f;  // 1/sqrt(128)
    const int g  = lane >> 2;
    const int tq = lane & 3;
    const int r0 = rw0 + g;
    const int r1 = r0 + 8;

    float mx0 = -1e30f, mx1 = -1e30f;
#pragma unroll
    for (int nt = 0; nt < 16; nt++) {
        int j0 = nt * 8 + tq * 2;
        int j1 = j0 + 1;
        float v;
        v = s[nt][0] * scale; if (j0 > r0) v = -1e30f; s[nt][0] = v; mx0 = fmaxf(mx0, v);
        v = s[nt][1] * scale; if (j1 > r0) v = -1e30f; s[nt][1] = v; mx0 = fmaxf(mx0, v);
        v = s[nt][2] * scale; if (j0 > r1) v = -1e30f; s[nt][2] = v; mx1 = fmaxf(mx1, v);
        v = s[nt][3] * scale; if (j1 > r1) v = -1e30f; s[nt][3] = v; mx1 = fmaxf(mx1, v);
    }
    mx0 = fmaxf(mx0, __shfl_xor_sync(0xffffffffu, mx0, 1));
    mx0 = fmaxf(mx0, __shfl_xor_sync(0xffffffffu, mx0, 2));
    mx1 = fmaxf(mx1, __shfl_xor_sync(0xffffffffu, mx1, 1));
    mx1 = fmaxf(mx1, __shfl_xor_sync(0xffffffffu, mx1, 2));

    float sum0 = 0.f, sum1 = 0.f;
#pragma unroll
    for (int nt = 0; nt < 16; nt++) {
        s[nt][0] = __expf(s[nt][0] - mx0); sum0 += s[nt][0];
        s[nt][1] = __expf(s[nt][1] - mx0); sum0 += s[nt][1];
        s[nt][2] = __expf(s[nt][2] - mx1); sum1 += s[nt][2];
        s[nt][3] = __expf(s[nt][3] - mx1); sum1 += s[nt][3];
    }
    sum0 += __shfl_xor_sync(0xffffffffu, sum0, 1);
    sum0 += __shfl_xor_sync(0xffffffffu, sum0, 2);
    sum1 += __shfl_xor_sync(0xffffffffu, sum1, 1);
    sum1 += __shfl_xor_sync(0xffffffffu, sum1, 2);
    const float inv0 = 1.f / sum0;
    const float inv1 = 1.f / sum1;

    // ----- O = P V (P split to bf16 hi/lo in regs), 3-pass -----
    float o[16][4];
#pragma unroll
    for (int nt = 0; nt < 16; nt++)
#pragma unroll
        for (int e = 0; e < 4; e++) o[nt][e] = 0.f;

#pragma unroll
    for (int kk = 0; kk < 8; kk++) {
        uint32_t aH[4], aL[4];
        split2b(s[2 * kk][0],     s[2 * kk][1],     aH[0], aL[0]);
        split2b(s[2 * kk][2],     s[2 * kk][3],     aH[1], aL[1]);
        split2b(s[2 * kk + 1][0], s[2 * kk + 1][1], aH[2], aL[2]);
        split2b(s[2 * kk + 1][2], s[2 * kk + 1][3], aH[3], aL[3]);
#pragma unroll
        for (int nt = 0; nt < 16; nt++) {
            uint32_t vH[2], vL[2];
            int l16  = lane & 15;
            int krow = kk * 16 + l16;
            int sw   = nt ^ (krow & 7);
            ldsm2ta(vH, smem_u32(sV + krow * 128 + sw * 8));
            ldsm2ta(vL, smem_u32(sV + (128 + krow) * 128 + sw * 8));
            mma_bf(o[nt], aH, vH);
            mma_bf(o[nt], aH, vL);
            mma_bf(o[nt], aL, vH);
        }
    }

    // ----- epilogue: single fp16 (input to proj GEMM) -----
    const size_t tok0 = t0 + r0;
    const size_t tok1 = t0 + r1;
#pragma unroll
    for (int nt = 0; nt < 16; nt++) {
        int col = h * DHEAD + nt * 8 + tq * 2;
        float v0 = o[nt][0] * inv0, v1 = o[nt][1] * inv0;
        float v2 = o[nt][2] * inv1, v3 = o[nt][3] * inv1;
        *reinterpret_cast<uint32_t*>(att + tok0 * CDIM + col) =
            pkh2(__float2half_rn(v0), __float2half_rn(v1));
        *reinterpret_cast<uint32_t*>(att + tok1 * CDIM + col) =
            pkh2(__float2half_rn(v2), __float2half_rn(v3));
    }
}

// ---------------------------------------------------------------------------
// Host launcher
// ---------------------------------------------------------------------------
extern "C" void kernel_launch(void* const* d_in, const int* in_sizes, int n_in,
                              void* d_out, int out_size) {
    const float* x  = (const float*)d_in[0];
    const float* wq = (const float*)d_in[1];
    const float* wp = (const float*)d_in[2];
    float* out = (float*)d_out;

    void *pX, *pWq, *pWp, *pQKV, *pA;
    cudaGetSymbolAddress(&pX,   g_X);
    cudaGetSymbolAddress(&pWq,  g_Wq);
    cudaGetSymbolAddress(&pWp,  g_Wp);
    cudaGetSymbolAddress(&pQKV, g_QKV);
    cudaGetSymbolAddress(&pA,   g_A);

    cudaFuncSetAttribute((const void*)gemm_fp16,
                         cudaFuncAttributeMaxDynamicSharedMemorySize, G_SMEM);
    cudaFuncSetAttribute((const void*)attn_kernel,
                         cudaFuncAttributeMaxDynamicSharedMemorySize, 196608);

    // 1) X, Wq, Wp -> fp16
    {
        int n4 = (MROWS * CDIM) / 4;
        cvt_h_kernel<<<n4 / 256, 256>>>((const float4*)x, (uint32_t*)pX, n4);
    }
    {
        int n4 = (CDIM * N_QKV) / 4;
        cvt_h_kernel<<<n4 / 256, 256>>>((const float4*)wq, (uint32_t*)pWq, n4);
    }
    {
        int n4 = (CDIM * CDIM) / 4;
        cvt_h_kernel<<<n4 / 256, 256>>>((const float4*)wp, (uint32_t*)pWp, n4);
    }

    // 2) QKV = X @ Wq -> fp32
    {
        dim3 grid(N_QKV / 128, MROWS / 128);  // (48, 256)
        gemm_fp16<<<grid, 256, G_SMEM>>>(
            (const __half*)pX, (const __half*)pWq, (float*)pQKV, N_QKV, CDIM);
    }

    // 3) blocked causal attention -> fp16
    attn_kernel<<<BATCH * NBLK * NHEAD, 256, 196608>>>(
        (const float*)pQKV, (__half*)pA);

    // 4) Y = A @ Wp -> fp32 final output
    {
        dim3 grid(CDIM / 128, MROWS / 128);   // (16, 256)
        gemm_fp16<<<grid, 256, G_SMEM>>>(
            (const __half*)pA, (const __half*)pWp, out, CDIM, CDIM);
    }
}

// round 8
// speedup vs baseline: 2.9122x; 1.0106x over previous
#include <cuda_runtime.h>
#include <cuda_bf16.h>
#include <cuda_fp16.h>
#include <cstdint>
#include <cstddef>

// ---------------------------------------------------------------------------
// Problem constants
// ---------------------------------------------------------------------------
constexpr int BATCH = 4;
constexpr int TSEQ  = 8192;
constexpr int CDIM  = 2048;
constexpr int DHEAD = 128;
constexpr int NBLK  = 64;            // TSEQ / 128
constexpr int MROWS = BATCH * TSEQ;  // 32768
constexpr int N_QKV = 3 * CDIM;      // 6144
constexpr int NHEAD = 16;

// ---------------------------------------------------------------------------
// Static scratch (no allocations allowed)
// ---------------------------------------------------------------------------
__device__ __align__(256) __half g_X  [(size_t)MROWS * CDIM];
__device__ __align__(256) __half g_Wq [(size_t)CDIM * N_QKV];   // [K][N] native
__device__ __align__(256) __half g_Wp [(size_t)CDIM * CDIM];    // [K][N] native
__device__ __align__(256) __half g_QKV[(size_t)MROWS * N_QKV];  // fp16 intermediates
__device__ __align__(256) __half g_A  [(size_t)MROWS * CDIM];

// ---------------------------------------------------------------------------
// Helpers
// ---------------------------------------------------------------------------
__device__ __forceinline__ uint32_t smem_u32(const void* p) {
    return (uint32_t)__cvta_generic_to_shared(p);
}
__device__ __forceinline__ void cp16s(uint32_t s, const void* g) {
    asm volatile("cp.async.cg.shared.global [%0], [%1], 16;" :: "r"(s), "l"(g));
}
__device__ __forceinline__ void cp_commit() {
    asm volatile("cp.async.commit_group;");
}
template <int N>
__device__ __forceinline__ void cp_wait() {
    asm volatile("cp.async.wait_group %0;" :: "n"(N));
}

__device__ __forceinline__ uint32_t pkh2(__half a, __half b) {
    __half2 t; t.x = a; t.y = b;
    return *reinterpret_cast<uint32_t*>(&t);
}

__device__ __forceinline__ void ldsm4a(uint32_t* d, uint32_t a) {
    asm volatile("ldmatrix.sync.aligned.m8n8.x4.shared.b16 {%0,%1,%2,%3}, [%4];"
                 : "=r"(d[0]), "=r"(d[1]), "=r"(d[2]), "=r"(d[3]) : "r"(a));
}
__device__ __forceinline__ void ldsm2a(uint32_t* d, uint32_t a) {
    asm volatile("ldmatrix.sync.aligned.m8n8.x2.shared.b16 {%0,%1}, [%2];"
                 : "=r"(d[0]), "=r"(d[1]) : "r"(a));
}
__device__ __forceinline__ void ldsm2ta(uint32_t* d, uint32_t a) {
    asm volatile("ldmatrix.sync.aligned.m8n8.x2.trans.shared.b16 {%0,%1}, [%2];"
                 : "=r"(d[0]), "=r"(d[1]) : "r"(a));
}
// fp16 mma
__device__ __forceinline__ void mma_h(float* c, const uint32_t* a, const uint32_t* b) {
    asm volatile(
        "mma.sync.aligned.m16n8k16.row.col.f32.f16.f16.f32 "
        "{%0,%1,%2,%3}, {%4,%5,%6,%7}, {%8,%9}, {%0,%1,%2,%3};"
        : "+f"(c[0]), "+f"(c[1]), "+f"(c[2]), "+f"(c[3])
        : "r"(a[0]), "r"(a[1]), "r"(a[2]), "r"(a[3]), "r"(b[0]), "r"(b[1]));
}

// ---------------------------------------------------------------------------
// fp32 -> fp16 (single, RN)
// ---------------------------------------------------------------------------
__global__ void cvt_h_kernel(const float4* __restrict__ src,
                             uint32_t* __restrict__ dst, int n4) {
    int i = blockIdx.x * blockDim.x + threadIdx.x;
    if (i >= n4) return;
    float4 v = src[i];
    dst[2 * i]     = pkh2(__float2half_rn(v.x), __float2half_rn(v.y));
    dst[2 * i + 1] = pkh2(__float2half_rn(v.z), __float2half_rn(v.w));
}

// ---------------------------------------------------------------------------
// fp16 single-pass GEMM: C[M,N] = A[M,K] @ B[K,N]
// BM=128, BN=128, BK=32, 4-stage cp.async ring, 256 threads (8 warps, 2x4),
// warp tile 64x32, 2 CTAs/SM. Loads for stage kt+3 issued BEFORE the mma
// block so LSU overlaps tensor pipe.
// Stage layout (16384 B): A @0 (8KB), B @8192 (8KB).
// OUT_HALF: write fp16 pairs to Ch; else fp32 to Cf.
// ---------------------------------------------------------------------------
constexpr int G_STAGE = 16384;
constexpr int G_SMEM  = 4 * G_STAGE;  // 65536

template <bool OUT_HALF>
__global__ void __launch_bounds__(256, 2) gemm_fp16(
    const __half* __restrict__ A, const __half* __restrict__ B,
    float* __restrict__ Cf, __half* __restrict__ Ch, int Nn, int Kk)
{
    extern __shared__ char smem[];
    const uint32_t sbase = smem_u32(smem);
    const int tid  = threadIdx.x;
    const int lane = tid & 31;
    const int wid  = tid >> 5;
    const int m0   = blockIdx.y * 128;
    const int n0   = blockIdx.x * 128;
    const int wm   = (wid >> 2) * 64;
    const int wn   = (wid & 3) * 32;

    // per-thread load slots: 2 A chunks + 2 B chunks of 16B
    const char* gA[2]; uint32_t sA[2];
#pragma unroll
    for (int i = 0; i < 2; i++) {
        int idx = tid + i * 256;
        int r = idx >> 2, ch = idx & 3;
        gA[i] = (const char*)(A + (size_t)(m0 + r) * Kk + ch * 8);
        sA[i] = sbase + r * 64 + ((ch ^ ((r >> 1) & 3)) * 16);
    }
    const char* gB[2]; uint32_t sB[2];
#pragma unroll
    for (int i = 0; i < 2; i++) {
        int idx = tid + i * 256;
        int r = idx >> 4, ch = idx & 15;
        gB[i] = (const char*)(B + (size_t)r * Nn + n0 + ch * 8);
        sB[i] = sbase + 8192 + r * 256 + ((ch ^ (r & 7)) * 16);
    }
    const size_t stepA = 64;                 // 32 halfs
    const size_t stepB = (size_t)32 * Nn * 2;

    const int NK = Kk / 32;

    // prologue: stages 0..2
#pragma unroll
    for (int s = 0; s < 3; s++) {
        uint32_t so = (uint32_t)(s * G_STAGE);
#pragma unroll
        for (int i = 0; i < 2; i++) cp16s(sA[i] + so, gA[i] + (size_t)s * stepA);
#pragma unroll
        for (int i = 0; i < 2; i++) cp16s(sB[i] + so, gB[i] + (size_t)s * stepB);
        cp_commit();
    }

    float c[4][4][4];
#pragma unroll
    for (int mt = 0; mt < 4; mt++)
#pragma unroll
        for (int nt = 0; nt < 4; nt++)
#pragma unroll
            for (int e = 0; e < 4; e++) c[mt][nt][e] = 0.f;

    for (int kt = 0; kt < NK; kt++) {
        cp_wait<2>();
        __syncthreads();

        // issue next-stage loads first: overlap with mma below
        {
            int kn = kt + 3;
            if (kn < NK) {
                uint32_t so = (uint32_t)((kn & 3) * G_STAGE);
#pragma unroll
                for (int i = 0; i < 2; i++) cp16s(sA[i] + so, gA[i] + (size_t)kn * stepA);
#pragma unroll
                for (int i = 0; i < 2; i++) cp16s(sB[i] + so, gB[i] + (size_t)kn * stepB);
            }
            cp_commit();
        }

        const uint32_t sbuf = sbase + (kt & 3) * G_STAGE;
#pragma unroll
        for (int kk = 0; kk < 2; kk++) {
            uint32_t b[4][2];
#pragma unroll
            for (int nt = 0; nt < 4; nt++) {
                int l16  = lane & 15;
                int krow = kk * 16 + l16;
                int ch   = (wn >> 3) + nt;
                int sw   = ch ^ (krow & 7);
                ldsm2ta(b[nt], sbuf + 8192 + krow * 256 + sw * 16);
            }
#pragma unroll
            for (int mt = 0; mt < 4; mt++) {
                int r  = wm + mt * 16 + (lane & 15);
                int ch = kk * 2 + (lane >> 4);
                int sw = ch ^ ((r >> 1) & 3);
                uint32_t a[4];
                ldsm4a(a, sbuf + r * 64 + sw * 16);
#pragma unroll
                for (int nt = 0; nt < 4; nt++)
                    mma_h(c[mt][nt], a, b[nt]);
            }
        }
    }

    // epilogue
#pragma unroll
    for (int mt = 0; mt < 4; mt++) {
#pragma unroll
        for (int nt = 0; nt < 4; nt++) {
            int row = m0 + wm + mt * 16 + (lane >> 2);
            int col = n0 + wn + nt * 8 + (lane & 3) * 2;
            if (OUT_HALF) {
                *reinterpret_cast<uint32_t*>(Ch + (size_t)row * Nn + col) =
                    pkh2(__float2half_rn(c[mt][nt][0]), __float2half_rn(c[mt][nt][1]));
                *reinterpret_cast<uint32_t*>(Ch + (size_t)(row + 8) * Nn + col) =
                    pkh2(__float2half_rn(c[mt][nt][2]), __float2half_rn(c[mt][nt][3]));
            } else {
                *reinterpret_cast<float2*>(Cf + (size_t)row * Nn + col) =
                    make_float2(c[mt][nt][0], c[mt][nt][1]);
                *reinterpret_cast<float2*>(Cf + (size_t)(row + 8) * Nn + col) =
                    make_float2(c[mt][nt][2], c[mt][nt][3]);
            }
        }
    }
}

// ---------------------------------------------------------------------------
// Attention: one CTA per (b, blk, h). fp16 QKV in, single-pass fp16 mma,
// causal triangular skipping. smem: sQ/sK/sV each [128][128] fp16 = 96KB.
// Warp w owns query rows [16w, 16w+16): QK^T only needs key tiles
// nt < 2w+2; PV only needs key blocks kk < w+1.
// ---------------------------------------------------------------------------
__global__ void __launch_bounds__(256, 1) attn_kernel(
    const __half* __restrict__ qkv, __half* __restrict__ att)
{
    extern __shared__ char smem[];
    __half* sQ = reinterpret_cast<__half*>(smem);            // [128][128]
    __half* sK = reinterpret_cast<__half*>(smem) + 16384;
    __half* sV = reinterpret_cast<__half*>(smem) + 32768;

    const int tid  = threadIdx.x;
    const int lane = tid & 31;
    const int wid  = tid >> 5;

    const int cta = blockIdx.x;
    const int h   = cta & 15;
    const int blk = (cta >> 4) & 63;
    const int b   = cta >> 10;
    const size_t t0 = (size_t)b * TSEQ + (size_t)blk * 128;

    // load Q,K,V: 3 tensors x 128 rows x 16 chunks(16B) = 6144 tasks
#pragma unroll
    for (int t = 0; t < 24; t++) {
        int idx = tid + t * 256;
        int tensor = idx >> 11;          // 0..2
        int rem = idx & 2047;
        int r  = rem >> 4;
        int ch = rem & 15;
        const __half* g = qkv + (t0 + r) * (size_t)N_QKV
                        + tensor * CDIM + h * DHEAD + ch * 8;
        __half* dstb = (tensor == 0) ? sQ : (tensor == 1) ? sK : sV;
        cp16s(smem_u32(dstb + r * 128 + ((ch ^ (r & 7)) * 8)), g);
    }
    cp_commit();
    cp_wait<0>();
    __syncthreads();

    // ----- S = Q K^T (warp tile 16 x 128), causal-skipped -----
    const int rw0  = wid * 16;
    const int nmax = 2 * wid + 2;        // key tiles needed (n8 granularity)

    float s[16][4];
#pragma unroll
    for (int nt = 0; nt < 16; nt++)
#pragma unroll
        for (int e = 0; e < 4; e++) s[nt][e] = 0.f;

#pragma unroll
    for (int kk = 0; kk < 8; kk++) {
        uint32_t q[4];
        {
            int r  = rw0 + (lane & 15);
            int ch = kk * 2 + (lane >> 4);
            int sw = ch ^ (r & 7);
            ldsm4a(q, smem_u32(sQ + r * 128 + sw * 8));
        }
        for (int nt = 0; nt < nmax; nt++) {
            uint32_t k[2];
            int l16  = lane & 15;
            int nrow = nt * 8 + (l16 & 7);
            int ch   = kk * 2 + (l16 >> 3);
            int sw   = ch ^ (nrow & 7);
            ldsm2a(k, smem_u32(sK + nrow * 128 + sw * 8));
            mma_h(s[nt], q, k);
        }
    }

    // ----- causal softmax (over valid tiles only) -----
    const float scale = 0.08838834764831845f;  // 1/sqrt(128)
    const int g  = lane >> 2;
    const int tq = lane & 3;
    const int r0 = rw0 + g;
    const int r1 = r0 + 8;

    float mx0 = -1e30f, mx1 = -1e30f;
    for (int nt = 0; nt < nmax; nt++) {
        int j0 = nt * 8 + tq * 2;
        int j1 = j0 + 1;
        float v;
        v = s[nt][0] * scale; if (j0 > r0) v = -1e30f; s[nt][0] = v; mx0 = fmaxf(mx0, v);
        v = s[nt][1] * scale; if (j1 > r0) v = -1e30f; s[nt][1] = v; mx0 = fmaxf(mx0, v);
        v = s[nt][2] * scale; if (j0 > r1) v = -1e30f; s[nt][2] = v; mx1 = fmaxf(mx1, v);
        v = s[nt][3] * scale; if (j1 > r1) v = -1e30f; s[nt][3] = v; mx1 = fmaxf(mx1, v);
    }
    mx0 = fmaxf(mx0, __shfl_xor_sync(0xffffffffu, mx0, 1));
    mx0 = fmaxf(mx0, __shfl_xor_sync(0xffffffffu, mx0, 2));
    mx1 = fmaxf(mx1, __shfl_xor_sync(0xffffffffu, mx1, 1));
    mx1 = fmaxf(mx1, __shfl_xor_sync(0xffffffffu, mx1, 2));

    float sum0 = 0.f, sum1 = 0.f;
    for (int nt = 0; nt < nmax; nt++) {
        s[nt][0] = __expf(s[nt][0] - mx0); sum0 += s[nt][0];
        s[nt][1] = __expf(s[nt][1] - mx0); sum0 += s[nt][1];
        s[nt][2] = __expf(s[nt][2] - mx1); sum1 += s[nt][2];
        s[nt][3] = __expf(s[nt][3] - mx1); sum1 += s[nt][3];
    }
    sum0 += __shfl_xor_sync(0xffffffffu, sum0, 1);
    sum0 += __shfl_xor_sync(0xffffffffu, sum0, 2);
    sum1 += __shfl_xor_sync(0xffffffffu, sum1, 1);
    sum1 += __shfl_xor_sync(0xffffffffu, sum1, 2);
    const float inv0 = 1.f / sum0;
    const float inv1 = 1.f / sum1;

    // ----- O = P V (P -> fp16 frags), key blocks kk < wid+1 -----
    float o[16][4];
#pragma unroll
    for (int nt = 0; nt < 16; nt++)
#pragma unroll
        for (int e = 0; e < 4; e++) o[nt][e] = 0.f;

    const int kmax = wid + 1;
    for (int kk = 0; kk < kmax; kk++) {
        uint32_t aP[4];
        aP[0] = pkh2(__float2half_rn(s[2 * kk][0]),     __float2half_rn(s[2 * kk][1]));
        aP[1] = pkh2(__float2half_rn(s[2 * kk][2]),     __float2half_rn(s[2 * kk][3]));
        aP[2] = pkh2(__float2half_rn(s[2 * kk + 1][0]), __float2half_rn(s[2 * kk + 1][1]));
        aP[3] = pkh2(__float2half_rn(s[2 * kk + 1][2]), __float2half_rn(s[2 * kk + 1][3]));
#pragma unroll
        for (int nt = 0; nt < 16; nt++) {
            uint32_t v[2];
            int l16  = lane & 15;
            int krow = kk * 16 + l16;
            int sw   = nt ^ (krow & 7);
            ldsm2ta(v, smem_u32(sV + krow * 128 + sw * 8));
            mma_h(o[nt], aP, v);
        }
    }

    // ----- epilogue: fp16 (input to proj GEMM) -----
    const size_t tok0 = t0 + r0;
    const size_t tok1 = t0 + r1;
#pragma unroll
    for (int nt = 0; nt < 16; nt++) {
        int col = h * DHEAD + nt * 8 + tq * 2;
        *reinterpret_cast<uint32_t*>(att + tok0 * CDIM + col) =
            pkh2(__float2half_rn(o[nt][0] * inv0), __float2half_rn(o[nt][1] * inv0));
        *reinterpret_cast<uint32_t*>(att + tok1 * CDIM + col) =
            pkh2(__float2half_rn(o[nt][2] * inv1), __float2half_rn(o[nt][3] * inv1));
    }
}

// ---------------------------------------------------------------------------
// Host launcher
// ---------------------------------------------------------------------------
extern "C" void kernel_launch(void* const* d_in, const int* in_sizes, int n_in,
                              void* d_out, int out_size) {
    const float* x  = (const float*)d_in[0];
    const float* wq = (const float*)d_in[1];
    const float* wp = (const float*)d_in[2];
    float* out = (float*)d_out;

    void *pX, *pWq, *pWp, *pQKV, *pA;
    cudaGetSymbolAddress(&pX,   g_X);
    cudaGetSymbolAddress(&pWq,  g_Wq);
    cudaGetSymbolAddress(&pWp,  g_Wp);
    cudaGetSymbolAddress(&pQKV, g_QKV);
    cudaGetSymbolAddress(&pA,   g_A);

    cudaFuncSetAttribute((const void*)gemm_fp16<true>,
                         cudaFuncAttributeMaxDynamicSharedMemorySize, G_SMEM);
    cudaFuncSetAttribute((const void*)gemm_fp16<false>,
                         cudaFuncAttributeMaxDynamicSharedMemorySize, G_SMEM);
    cudaFuncSetAttribute((const void*)attn_kernel,
                         cudaFuncAttributeMaxDynamicSharedMemorySize, 98304);

    // 1) X, Wq, Wp -> fp16
    {
        int n4 = (MROWS * CDIM) / 4;
        cvt_h_kernel<<<n4 / 256, 256>>>((const float4*)x, (uint32_t*)pX, n4);
    }
    {
        int n4 = (CDIM * N_QKV) / 4;
        cvt_h_kernel<<<n4 / 256, 256>>>((const float4*)wq, (uint32_t*)pWq, n4);
    }
    {
        int n4 = (CDIM * CDIM) / 4;
        cvt_h_kernel<<<n4 / 256, 256>>>((const float4*)wp, (uint32_t*)pWp, n4);
    }

    // 2) QKV = X @ Wq -> fp16
    {
        dim3 grid(N_QKV / 128, MROWS / 128);  // (48, 256)
        gemm_fp16<true><<<grid, 256, G_SMEM>>>(
            (const __half*)pX, (const __half*)pWq, nullptr, (__half*)pQKV,
            N_QKV, CDIM);
    }

    // 3) blocked causal attention -> fp16
    attn_kernel<<<BATCH * NBLK * NHEAD, 256, 98304>>>(
        (const __half*)pQKV, (__half*)pA);

    // 4) Y = A @ Wp -> fp32 final output
    {
        dim3 grid(CDIM / 128, MROWS / 128);   // (16, 256)
        gemm_fp16<false><<<grid, 256, G_SMEM>>>(
            (const __half*)pA, (const __half*)pWp, out, nullptr, CDIM, CDIM);
    }
}

// round 9
// speedup vs baseline: 3.1298x; 1.0747x over previous
#include <cuda_runtime.h>
#include <cuda_bf16.h>
#include <cuda_fp16.h>
#include <cstdint>
#include <cstddef>

// ---------------------------------------------------------------------------
// Problem constants
// ---------------------------------------------------------------------------
constexpr int BATCH = 4;
constexpr int TSEQ  = 8192;
constexpr int CDIM  = 2048;
constexpr int DHEAD = 128;
constexpr int NBLK  = 64;            // TSEQ / 128
constexpr int MROWS = BATCH * TSEQ;  // 32768
constexpr int N_QKV = 3 * CDIM;      // 6144
constexpr int NHEAD = 16;

// ---------------------------------------------------------------------------
// Static scratch (no allocations allowed)
// ---------------------------------------------------------------------------
__device__ __align__(256) __half g_X  [(size_t)MROWS * CDIM];
__device__ __align__(256) __half g_Wq [(size_t)CDIM * N_QKV];   // [K][N] native
__device__ __align__(256) __half g_Wp [(size_t)CDIM * CDIM];    // [K][N] native
__device__ __align__(256) __half g_QKV[(size_t)MROWS * N_QKV];  // fp16 intermediates
__device__ __align__(256) __half g_A  [(size_t)MROWS * CDIM];

// ---------------------------------------------------------------------------
// Helpers
// ---------------------------------------------------------------------------
__device__ __forceinline__ uint32_t smem_u32(const void* p) {
    return (uint32_t)__cvta_generic_to_shared(p);
}
__device__ __forceinline__ void cp16s(uint32_t s, const void* g) {
    asm volatile("cp.async.cg.shared.global [%0], [%1], 16;" :: "r"(s), "l"(g));
}
__device__ __forceinline__ void cp_commit() {
    asm volatile("cp.async.commit_group;");
}
template <int N>
__device__ __forceinline__ void cp_wait() {
    asm volatile("cp.async.wait_group %0;" :: "n"(N));
}

__device__ __forceinline__ uint32_t pkh2(__half a, __half b) {
    __half2 t; t.x = a; t.y = b;
    return *reinterpret_cast<uint32_t*>(&t);
}

__device__ __forceinline__ void ldsm4a(uint32_t* d, uint32_t a) {
    asm volatile("ldmatrix.sync.aligned.m8n8.x4.shared.b16 {%0,%1,%2,%3}, [%4];"
                 : "=r"(d[0]), "=r"(d[1]), "=r"(d[2]), "=r"(d[3]) : "r"(a));
}
__device__ __forceinline__ void ldsm4ta(uint32_t* d, uint32_t a) {
    asm volatile("ldmatrix.sync.aligned.m8n8.x4.trans.shared.b16 {%0,%1,%2,%3}, [%4];"
                 : "=r"(d[0]), "=r"(d[1]), "=r"(d[2]), "=r"(d[3]) : "r"(a));
}
__device__ __forceinline__ void ldsm2a(uint32_t* d, uint32_t a) {
    asm volatile("ldmatrix.sync.aligned.m8n8.x2.shared.b16 {%0,%1}, [%2];"
                 : "=r"(d[0]), "=r"(d[1]) : "r"(a));
}
__device__ __forceinline__ void ldsm2ta(uint32_t* d, uint32_t a) {
    asm volatile("ldmatrix.sync.aligned.m8n8.x2.trans.shared.b16 {%0,%1}, [%2];"
                 : "=r"(d[0]), "=r"(d[1]) : "r"(a));
}
// fp16 mma
__device__ __forceinline__ void mma_h(float* c, const uint32_t* a, const uint32_t* b) {
    asm volatile(
        "mma.sync.aligned.m16n8k16.row.col.f32.f16.f16.f32 "
        "{%0,%1,%2,%3}, {%4,%5,%6,%7}, {%8,%9}, {%0,%1,%2,%3};"
        : "+f"(c[0]), "+f"(c[1]), "+f"(c[2]), "+f"(c[3])
        : "r"(a[0]), "r"(a[1]), "r"(a[2]), "r"(a[3]), "r"(b[0]), "r"(b[1]));
}

// ---------------------------------------------------------------------------
// fp32 -> fp16 (single, RN)
// ---------------------------------------------------------------------------
__global__ void cvt_h_kernel(const float4* __restrict__ src,
                             uint32_t* __restrict__ dst, int n4) {
    int i = blockIdx.x * blockDim.x + threadIdx.x;
    if (i >= n4) return;
    float4 v = src[i];
    dst[2 * i]     = pkh2(__float2half_rn(v.x), __float2half_rn(v.y));
    dst[2 * i + 1] = pkh2(__float2half_rn(v.z), __float2half_rn(v.w));
}

// ---------------------------------------------------------------------------
// fp16 single-pass GEMM: C[M,N] = A[M,K] @ B[K,N]
// BM=128, BN=128, BK=64, 3-stage cp.async ring, 256 threads (8 warps, 2x4),
// warp tile 64x32, 2 CTAs/SM. B fragments via ldmatrix.x4.trans (2 frags/instr).
// Stage layout (32768 B): A @0 (16KB: 128 rows x 128B SW128), B @16384
// (16KB: 64 krows x 256B).
// OUT_HALF: write fp16 pairs to Ch; else fp32 to Cf.
// ---------------------------------------------------------------------------
constexpr int G_STAGE = 32768;
constexpr int G_BOFF  = 16384;
constexpr int G_SMEM  = 3 * G_STAGE;  // 98304

template <bool OUT_HALF>
__global__ void __launch_bounds__(256, 2) gemm_fp16(
    const __half* __restrict__ A, const __half* __restrict__ B,
    float* __restrict__ Cf, __half* __restrict__ Ch, int Nn, int Kk)
{
    extern __shared__ char smem[];
    const uint32_t sbase = smem_u32(smem);
    const int tid  = threadIdx.x;
    const int lane = tid & 31;
    const int wid  = tid >> 5;
    const int m0   = blockIdx.y * 128;
    const int n0   = blockIdx.x * 128;
    const int wm   = (wid >> 2) * 64;
    const int wn   = (wid & 3) * 32;

    // per-thread load slots: 4 A chunks + 4 B chunks of 16B per stage
    // A: 128 rows x 8 chunks (128B rows, SW128)
    const char* gA[4]; uint32_t sA[4];
#pragma unroll
    for (int i = 0; i < 4; i++) {
        int idx = tid + i * 256;
        int r = idx >> 3, ch = idx & 7;
        gA[i] = (const char*)(A + (size_t)(m0 + r) * Kk + ch * 8);
        sA[i] = sbase + r * 128 + ((ch ^ (r & 7)) * 16);
    }
    // B: 64 krows x 16 chunks (256B rows)
    const char* gB[4]; uint32_t sB[4];
#pragma unroll
    for (int i = 0; i < 4; i++) {
        int idx = tid + i * 256;
        int r = idx >> 4, ch = idx & 15;
        gB[i] = (const char*)(B + (size_t)r * Nn + n0 + ch * 8);
        sB[i] = sbase + G_BOFF + r * 256 + ((ch ^ (r & 7)) * 16);
    }
    const size_t stepA = 128;                // 64 halfs
    const size_t stepB = (size_t)64 * Nn * 2;

    const int NK = Kk / 64;

    // prologue: stages 0..1
#pragma unroll
    for (int s = 0; s < 2; s++) {
        uint32_t so = (uint32_t)(s * G_STAGE);
#pragma unroll
        for (int i = 0; i < 4; i++) cp16s(sA[i] + so, gA[i] + (size_t)s * stepA);
#pragma unroll
        for (int i = 0; i < 4; i++) cp16s(sB[i] + so, gB[i] + (size_t)s * stepB);
        cp_commit();
    }

    float c[4][4][4];
#pragma unroll
    for (int mt = 0; mt < 4; mt++)
#pragma unroll
        for (int nt = 0; nt < 4; nt++)
#pragma unroll
            for (int e = 0; e < 4; e++) c[mt][nt][e] = 0.f;

    int sidx = 0;                            // stage index of kt
    for (int kt = 0; kt < NK; kt++) {
        cp_wait<1>();
        __syncthreads();

        // issue stage kt+2 (buffer last consumed in iter kt-1; safe after barrier)
        {
            int kn = kt + 2;
            if (kn < NK) {
                int sn = sidx + 2; if (sn >= 3) sn -= 3;
                uint32_t so = (uint32_t)(sn * G_STAGE);
#pragma unroll
                for (int i = 0; i < 4; i++) cp16s(sA[i] + so, gA[i] + (size_t)kn * stepA);
#pragma unroll
                for (int i = 0; i < 4; i++) cp16s(sB[i] + so, gB[i] + (size_t)kn * stepB);
            }
            cp_commit();
        }

        const uint32_t sbuf = sbase + sidx * G_STAGE;
#pragma unroll
        for (int kk = 0; kk < 4; kk++) {
            // B: two ldsm4t give all four n8k16 frags
            uint32_t bb[2][4];
#pragma unroll
            for (int p = 0; p < 2; p++) {
                int krow = kk * 16 + (lane & 15);
                int ch   = (wn >> 3) + p * 2 + (lane >> 4);
                int sw   = ch ^ (krow & 7);
                ldsm4ta(bb[p], sbuf + G_BOFF + krow * 256 + sw * 16);
            }
#pragma unroll
            for (int mt = 0; mt < 4; mt++) {
                int r  = wm + mt * 16 + (lane & 15);
                int ch = kk * 2 + (lane >> 4);
                int sw = ch ^ (r & 7);
                uint32_t a[4];
                ldsm4a(a, sbuf + r * 128 + sw * 16);
                mma_h(c[mt][0], a, &bb[0][0]);
                mma_h(c[mt][1], a, &bb[0][2]);
                mma_h(c[mt][2], a, &bb[1][0]);
                mma_h(c[mt][3], a, &bb[1][2]);
            }
        }
        sidx++; if (sidx >= 3) sidx = 0;
    }

    // epilogue
#pragma unroll
    for (int mt = 0; mt < 4; mt++) {
#pragma unroll
        for (int nt = 0; nt < 4; nt++) {
            int row = m0 + wm + mt * 16 + (lane >> 2);
            int col = n0 + wn + nt * 8 + (lane & 3) * 2;
            if (OUT_HALF) {
                *reinterpret_cast<uint32_t*>(Ch + (size_t)row * Nn + col) =
                    pkh2(__float2half_rn(c[mt][nt][0]), __float2half_rn(c[mt][nt][1]));
                *reinterpret_cast<uint32_t*>(Ch + (size_t)(row + 8) * Nn + col) =
                    pkh2(__float2half_rn(c[mt][nt][2]), __float2half_rn(c[mt][nt][3]));
            } else {
                *reinterpret_cast<float2*>(Cf + (size_t)row * Nn + col) =
                    make_float2(c[mt][nt][0], c[mt][nt][1]);
                *reinterpret_cast<float2*>(Cf + (size_t)(row + 8) * Nn + col) =
                    make_float2(c[mt][nt][2], c[mt][nt][3]);
            }
        }
    }
}

// ---------------------------------------------------------------------------
// Attention: one CTA per (b, blk, h). fp16 QKV in, single-pass fp16 mma,
// causal triangular skipping. smem: sQ/sK/sV each [128][128] fp16 = 96KB.
// Warp w owns query rows [16w, 16w+16): QK^T only needs key tiles
// nt < 2w+2; PV only needs key blocks kk < w+1.
// ---------------------------------------------------------------------------
__global__ void __launch_bounds__(256, 1) attn_kernel(
    const __half* __restrict__ qkv, __half* __restrict__ att)
{
    extern __shared__ char smem[];
    __half* sQ = reinterpret_cast<__half*>(smem);            // [128][128]
    __half* sK = reinterpret_cast<__half*>(smem) + 16384;
    __half* sV = reinterpret_cast<__half*>(smem) + 32768;

    const int tid  = threadIdx.x;
    const int lane = tid & 31;
    const int wid  = tid >> 5;

    const int cta = blockIdx.x;
    const int h   = cta & 15;
    const int blk = (cta >> 4) & 63;
    const int b   = cta >> 10;
    const size_t t0 = (size_t)b * TSEQ + (size_t)blk * 128;

    // load Q,K,V: 3 tensors x 128 rows x 16 chunks(16B) = 6144 tasks
#pragma unroll
    for (int t = 0; t < 24; t++) {
        int idx = tid + t * 256;
        int tensor = idx >> 11;          // 0..2
        int rem = idx & 2047;
        int r  = rem >> 4;
        int ch = rem & 15;
        const __half* g = qkv + (t0 + r) * (size_t)N_QKV
                        + tensor * CDIM + h * DHEAD + ch * 8;
        __half* dstb = (tensor == 0) ? sQ : (tensor == 1) ? sK : sV;
        cp16s(smem_u32(dstb + r * 128 + ((ch ^ (r & 7)) * 8)), g);
    }
    cp_commit();
    cp_wait<0>();
    __syncthreads();

    // ----- S = Q K^T (warp tile 16 x 128), causal-skipped -----
    const int rw0  = wid * 16;
    const int nmax = 2 * wid + 2;        // key tiles needed (n8 granularity)

    float s[16][4];
#pragma unroll
    for (int nt = 0; nt < 16; nt++)
#pragma unroll
        for (int e = 0; e < 4; e++) s[nt][e] = 0.f;

#pragma unroll
    for (int kk = 0; kk < 8; kk++) {
        uint32_t q[4];
        {
            int r  = rw0 + (lane & 15);
            int ch = kk * 2 + (lane >> 4);
            int sw = ch ^ (r & 7);
            ldsm4a(q, smem_u32(sQ + r * 128 + sw * 8));
        }
        for (int nt = 0; nt < nmax; nt++) {
            uint32_t k[2];
            int l16  = lane & 15;
            int nrow = nt * 8 + (l16 & 7);
            int ch   = kk * 2 + (l16 >> 3);
            int sw   = ch ^ (nrow & 7);
            ldsm2a(k, smem_u32(sK + nrow * 128 + sw * 8));
            mma_h(s[nt], q, k);
        }
    }

    // ----- causal softmax (over valid tiles only) -----
    const float scale = 0.08838834764831845f;  // 1/sqrt(128)
    const int g  = lane >> 2;
    const int tq = lane & 3;
    const int r0 = rw0 + g;
    const int r1 = r0 + 8;

    float mx0 = -1e30f, mx1 = -1e30f;
    for (int nt = 0; nt < nmax; nt++) {
        int j0 = nt * 8 + tq * 2;
        int j1 = j0 + 1;
        float v;
        v = s[nt][0] * scale; if (j0 > r0) v = -1e30f; s[nt][0] = v; mx0 = fmaxf(mx0, v);
        v = s[nt][1] * scale; if (j1 > r0) v = -1e30f; s[nt][1] = v; mx0 = fmaxf(mx0, v);
        v = s[nt][2] * scale; if (j0 > r1) v = -1e30f; s[nt][2] = v; mx1 = fmaxf(mx1, v);
        v = s[nt][3] * scale; if (j1 > r1) v = -1e30f; s[nt][3] = v; mx1 = fmaxf(mx1, v);
    }
    mx0 = fmaxf(mx0, __shfl_xor_sync(0xffffffffu, mx0, 1));
    mx0 = fmaxf(mx0, __shfl_xor_sync(0xffffffffu, mx0, 2));
    mx1 = fmaxf(mx1, __shfl_xor_sync(0xffffffffu, mx1, 1));
    mx1 = fmaxf(mx1, __shfl_xor_sync(0xffffffffu, mx1, 2));

    float sum0 = 0.f, sum1 = 0.f;
    for (int nt = 0; nt < nmax; nt++) {
        s[nt][0] = __expf(s[nt][0] - mx0); sum0 += s[nt][0];
        s[nt][1] = __expf(s[nt][1] - mx0); sum0 += s[nt][1];
        s[nt][2] = __expf(s[nt][2] - mx1); sum1 += s[nt][2];
        s[nt][3] = __expf(s[nt][3] - mx1); sum1 += s[nt][3];
    }
    sum0 += __shfl_xor_sync(0xffffffffu, sum0, 1);
    sum0 += __shfl_xor_sync(0xffffffffu, sum0, 2);
    sum1 += __shfl_xor_sync(0xffffffffu, sum1, 1);
    sum1 += __shfl_xor_sync(0xffffffffu, sum1, 2);
    const float inv0 = 1.f / sum0;
    const float inv1 = 1.f / sum1;

    // ----- O = P V (P -> fp16 frags), key blocks kk < wid+1 -----
    float o[16][4];
#pragma unroll
    for (int nt = 0; nt < 16; nt++)
#pragma unroll
        for (int e = 0; e < 4; e++) o[nt][e] = 0.f;

    const int kmax = wid + 1;
    for (int kk = 0; kk < kmax; kk++) {
        uint32_t aP[4];
        aP[0] = pkh2(__float2half_rn(s[2 * kk][0]),     __float2half_rn(s[2 * kk][1]));
        aP[1] = pkh2(__float2half_rn(s[2 * kk][2]),     __float2half_rn(s[2 * kk][3]));
        aP[2] = pkh2(__float2half_rn(s[2 * kk + 1][0]), __float2half_rn(s[2 * kk + 1][1]));
        aP[3] = pkh2(__float2half_rn(s[2 * kk + 1][2]), __float2half_rn(s[2 * kk + 1][3]));
#pragma unroll
        for (int nt = 0; nt < 16; nt++) {
            uint32_t v[2];
            int l16  = lane & 15;
            int krow = kk * 16 + l16;
            int sw   = nt ^ (krow & 7);
            ldsm2ta(v, smem_u32(sV + krow * 128 + sw * 8));
            mma_h(o[nt], aP, v);
        }
    }

    // ----- epilogue: fp16 (input to proj GEMM) -----
    const size_t tok0 = t0 + r0;
    const size_t tok1 = t0 + r1;
#pragma unroll
    for (int nt = 0; nt < 16; nt++) {
        int col = h * DHEAD + nt * 8 + tq * 2;
        *reinterpret_cast<uint32_t*>(att + tok0 * CDIM + col) =
            pkh2(__float2half_rn(o[nt][0] * inv0), __float2half_rn(o[nt][1] * inv0));
        *reinterpret_cast<uint32_t*>(att + tok1 * CDIM + col) =
            pkh2(__float2half_rn(o[nt][2] * inv1), __float2half_rn(o[nt][3] * inv1));
    }
}

// ---------------------------------------------------------------------------
// Host launcher
// ---------------------------------------------------------------------------
extern "C" void kernel_launch(void* const* d_in, const int* in_sizes, int n_in,
                              void* d_out, int out_size) {
    const float* x  = (const float*)d_in[0];
    const float* wq = (const float*)d_in[1];
    const float* wp = (const float*)d_in[2];
    float* out = (float*)d_out;

    void *pX, *pWq, *pWp, *pQKV, *pA;
    cudaGetSymbolAddress(&pX,   g_X);
    cudaGetSymbolAddress(&pWq,  g_Wq);
    cudaGetSymbolAddress(&pWp,  g_Wp);
    cudaGetSymbolAddress(&pQKV, g_QKV);
    cudaGetSymbolAddress(&pA,   g_A);

    cudaFuncSetAttribute((const void*)gemm_fp16<true>,
                         cudaFuncAttributeMaxDynamicSharedMemorySize, G_SMEM);
    cudaFuncSetAttribute((const void*)gemm_fp16<false>,
                         cudaFuncAttributeMaxDynamicSharedMemorySize, G_SMEM);
    cudaFuncSetAttribute((const void*)attn_kernel,
                         cudaFuncAttributeMaxDynamicSharedMemorySize, 98304);

    // 1) X, Wq, Wp -> fp16
    {
        int n4 = (MROWS * CDIM) / 4;
        cvt_h_kernel<<<n4 / 256, 256>>>((const float4*)x, (uint32_t*)pX, n4);
    }
    {
        int n4 = (CDIM * N_QKV) / 4;
        cvt_h_kernel<<<n4 / 256, 256>>>((const float4*)wq, (uint32_t*)pWq, n4);
    }
    {
        int n4 = (CDIM * CDIM) / 4;
        cvt_h_kernel<<<n4 / 256, 256>>>((const float4*)wp, (uint32_t*)pWp, n4);
    }

    // 2) QKV = X @ Wq -> fp16
    {
        dim3 grid(N_QKV / 128, MROWS / 128);  // (48, 256)
        gemm_fp16<true><<<grid, 256, G_SMEM>>>(
            (const __half*)pX, (const __half*)pWq, nullptr, (__half*)pQKV,
            N_QKV, CDIM);
    }

    // 3) blocked causal attention -> fp16
    attn_kernel<<<BATCH * NBLK * NHEAD, 256, 98304>>>(
        (const __half*)pQKV, (__half*)pA);

    // 4) Y = A @ Wp -> fp32 final output
    {
        dim3 grid(CDIM / 128, MROWS / 128);   // (16, 256)
        gemm_fp16<false><<<grid, 256, G_SMEM>>>(
            (const __half*)pA, (const __half*)pWp, out, nullptr, CDIM, CDIM);
    }
}

// round 10
// speedup vs baseline: 3.1823x; 1.0168x over previous
#include <cuda_runtime.h>
#include <cuda_bf16.h>
#include <cuda_fp16.h>
#include <cstdint>
#include <cstddef>

// ---------------------------------------------------------------------------
// Problem constants
// ---------------------------------------------------------------------------
constexpr int BATCH = 4;
constexpr int TSEQ  = 8192;
constexpr int CDIM  = 2048;
constexpr int DHEAD = 128;
constexpr int NBLK  = 64;            // TSEQ / 128
constexpr int MROWS = BATCH * TSEQ;  // 32768
constexpr int N_QKV = 3 * CDIM;      // 6144
constexpr int NHEAD = 16;

// ---------------------------------------------------------------------------
// Static scratch (no allocations allowed)
// ---------------------------------------------------------------------------
__device__ __align__(256) __half g_X  [(size_t)MROWS * CDIM];
__device__ __align__(256) __half g_Wq [(size_t)CDIM * N_QKV];   // [K][N] native
__device__ __align__(256) __half g_Wp [(size_t)CDIM * CDIM];    // [K][N] native
__device__ __align__(256) __half g_QKV[(size_t)MROWS * N_QKV];  // fp16 intermediates
__device__ __align__(256) __half g_A  [(size_t)MROWS * CDIM];

// ---------------------------------------------------------------------------
// Helpers
// ---------------------------------------------------------------------------
__device__ __forceinline__ uint32_t smem_u32(const void* p) {
    return (uint32_t)__cvta_generic_to_shared(p);
}
__device__ __forceinline__ void cp16s(uint32_t s, const void* g) {
    asm volatile("cp.async.cg.shared.global [%0], [%1], 16;" :: "r"(s), "l"(g));
}
__device__ __forceinline__ void cp_commit() {
    asm volatile("cp.async.commit_group;");
}
template <int N>
__device__ __forceinline__ void cp_wait() {
    asm volatile("cp.async.wait_group %0;" :: "n"(N));
}

__device__ __forceinline__ uint32_t pkh2(__half a, __half b) {
    __half2 t; t.x = a; t.y = b;
    return *reinterpret_cast<uint32_t*>(&t);
}

__device__ __forceinline__ void ldsm4a(uint32_t* d, uint32_t a) {
    asm volatile("ldmatrix.sync.aligned.m8n8.x4.shared.b16 {%0,%1,%2,%3}, [%4];"
                 : "=r"(d[0]), "=r"(d[1]), "=r"(d[2]), "=r"(d[3]) : "r"(a));
}
__device__ __forceinline__ void ldsm4ta(uint32_t* d, uint32_t a) {
    asm volatile("ldmatrix.sync.aligned.m8n8.x4.trans.shared.b16 {%0,%1,%2,%3}, [%4];"
                 : "=r"(d[0]), "=r"(d[1]), "=r"(d[2]), "=r"(d[3]) : "r"(a));
}
__device__ __forceinline__ void ldsm2a(uint32_t* d, uint32_t a) {
    asm volatile("ldmatrix.sync.aligned.m8n8.x2.shared.b16 {%0,%1}, [%2];"
                 : "=r"(d[0]), "=r"(d[1]) : "r"(a));
}
__device__ __forceinline__ void ldsm2ta(uint32_t* d, uint32_t a) {
    asm volatile("ldmatrix.sync.aligned.m8n8.x2.trans.shared.b16 {%0,%1}, [%2];"
                 : "=r"(d[0]), "=r"(d[1]) : "r"(a));
}
// fp16 mma
__device__ __forceinline__ void mma_h(float* c, const uint32_t* a, const uint32_t* b) {
    asm volatile(
        "mma.sync.aligned.m16n8k16.row.col.f32.f16.f16.f32 "
        "{%0,%1,%2,%3}, {%4,%5,%6,%7}, {%8,%9}, {%0,%1,%2,%3};"
        : "+f"(c[0]), "+f"(c[1]), "+f"(c[2]), "+f"(c[3])
        : "r"(a[0]), "r"(a[1]), "r"(a[2]), "r"(a[3]), "r"(b[0]), "r"(b[1]));
}

// ---------------------------------------------------------------------------
// fp32 -> fp16 (single, RN)
// ---------------------------------------------------------------------------
__global__ void cvt_h_kernel(const float4* __restrict__ src,
                             uint32_t* __restrict__ dst, int n4) {
    int i = blockIdx.x * blockDim.x + threadIdx.x;
    if (i >= n4) return;
    float4 v = src[i];
    dst[2 * i]     = pkh2(__float2half_rn(v.x), __float2half_rn(v.y));
    dst[2 * i + 1] = pkh2(__float2half_rn(v.z), __float2half_rn(v.w));
}

// ---------------------------------------------------------------------------
// fp16 single-pass GEMM: C[M,N] = A[M,K] @ B[K,N]
// BM=128, BN=128, BK=64, 3-stage cp.async ring.
// 128 threads = 4 warps (2m x 2n), warp tile 64x64, 2 CTAs/SM.
// Per k16 step a warp does 4 A-ldsm4 + 4 B-ldsm4t for 32 mma (128 B/mma).
// Stage layout (32768 B): A @0 (16KB: 128 rows x 128B SW128),
//                         B @16384 (16KB: 64 krows x 256B).
// OUT_HALF: write fp16 pairs to Ch; else fp32 to Cf.
// ---------------------------------------------------------------------------
constexpr int G_STAGE = 32768;
constexpr int G_BOFF  = 16384;
constexpr int G_SMEM  = 3 * G_STAGE;  // 98304

template <bool OUT_HALF>
__global__ void __launch_bounds__(128, 2) gemm_fp16(
    const __half* __restrict__ A, const __half* __restrict__ B,
    float* __restrict__ Cf, __half* __restrict__ Ch, int Nn, int Kk)
{
    extern __shared__ char smem[];
    const uint32_t sbase = smem_u32(smem);
    const int tid  = threadIdx.x;
    const int lane = tid & 31;
    const int wid  = tid >> 5;
    const int m0   = blockIdx.y * 128;
    const int n0   = blockIdx.x * 128;
    const int wm   = (wid >> 1) * 64;
    const int wn   = (wid & 1) * 64;

    // --- load geometry (base + stride; swizzle bits invariant under row step) ---
    // A: 128 rows x 8 chunks(16B) = 1024 tasks, 8 per thread, row step 16
    const int ra = tid >> 3, ca = tid & 7;
    const char* gA0 = (const char*)(A + (size_t)(m0 + ra) * Kk + ca * 8);
    const uint32_t sA0 = sbase + ra * 128 + ((ca ^ (ra & 7)) * 16);
    const size_t rowA = (size_t)16 * Kk * 2;       // +16 rows
    // B: 64 krows x 16 chunks = 1024 tasks, 8 per thread, krow step 8
    const int rb = tid >> 4, cb = tid & 15;
    const char* gB0 = (const char*)(B + (size_t)rb * Nn + n0 + cb * 8);
    const uint32_t sB0 = sbase + G_BOFF + rb * 256 + ((cb ^ (rb & 7)) * 16);
    const size_t rowB = (size_t)8 * Nn * 2;        // +8 krows

    const size_t stepA = 128;                      // k-tile: 64 halfs
    const size_t stepB = (size_t)64 * Nn * 2;

    const int NK = Kk / 64;

    // prologue: stages 0..1
#pragma unroll
    for (int s = 0; s < 2; s++) {
        uint32_t so = (uint32_t)(s * G_STAGE);
        const char* ga = gA0 + (size_t)s * stepA;
        const char* gb = gB0 + (size_t)s * stepB;
#pragma unroll
        for (int i = 0; i < 8; i++)
            cp16s(sA0 + so + i * (16 * 128), ga + (size_t)i * rowA);
#pragma unroll
        for (int i = 0; i < 8; i++)
            cp16s(sB0 + so + i * (8 * 256), gb + (size_t)i * rowB);
        cp_commit();
    }

    float c[4][8][4];
#pragma unroll
    for (int mt = 0; mt < 4; mt++)
#pragma unroll
        for (int nt = 0; nt < 8; nt++)
#pragma unroll
            for (int e = 0; e < 4; e++) c[mt][nt][e] = 0.f;

    int sidx = 0;                            // stage index of kt
    for (int kt = 0; kt < NK; kt++) {
        cp_wait<1>();
        __syncthreads();

        // issue stage kt+2 (buffer last consumed in iter kt-1; safe after barrier)
        {
            int kn = kt + 2;
            if (kn < NK) {
                int sn = sidx + 2; if (sn >= 3) sn -= 3;
                uint32_t so = (uint32_t)(sn * G_STAGE);
                const char* ga = gA0 + (size_t)kn * stepA;
                const char* gb = gB0 + (size_t)kn * stepB;
#pragma unroll
                for (int i = 0; i < 8; i++)
                    cp16s(sA0 + so + i * (16 * 128), ga + (size_t)i * rowA);
#pragma unroll
                for (int i = 0; i < 8; i++)
                    cp16s(sB0 + so + i * (8 * 256), gb + (size_t)i * rowB);
            }
            cp_commit();
        }

        const uint32_t sbuf = sbase + sidx * G_STAGE;
#pragma unroll
        for (int kk = 0; kk < 4; kk++) {
            // B: four ldsm4t give all eight n8k16 frags for the 64-wide warp tile
            uint32_t bb[4][4];
#pragma unroll
            for (int p = 0; p < 4; p++) {
                int krow = kk * 16 + (lane & 15);
                int ch   = (wn >> 3) + p * 2 + (lane >> 4);
                int sw   = ch ^ (krow & 7);
                ldsm4ta(bb[p], sbuf + G_BOFF + krow * 256 + sw * 16);
            }
            // A: four ldsm4, one per 16-row tile
            uint32_t aa[4][4];
#pragma unroll
            for (int mt = 0; mt < 4; mt++) {
                int r  = wm + mt * 16 + (lane & 15);
                int ch = kk * 2 + (lane >> 4);
                int sw = ch ^ (r & 7);
                ldsm4a(aa[mt], sbuf + r * 128 + sw * 16);
            }
#pragma unroll
            for (int mt = 0; mt < 4; mt++)
#pragma unroll
                for (int p = 0; p < 4; p++) {
                    mma_h(c[mt][2 * p],     aa[mt], &bb[p][0]);
                    mma_h(c[mt][2 * p + 1], aa[mt], &bb[p][2]);
                }
        }
        sidx++; if (sidx >= 3) sidx = 0;
    }

    // epilogue
#pragma unroll
    for (int mt = 0; mt < 4; mt++) {
#pragma unroll
        for (int nt = 0; nt < 8; nt++) {
            int row = m0 + wm + mt * 16 + (lane >> 2);
            int col = n0 + wn + nt * 8 + (lane & 3) * 2;
            if (OUT_HALF) {
                *reinterpret_cast<uint32_t*>(Ch + (size_t)row * Nn + col) =
                    pkh2(__float2half_rn(c[mt][nt][0]), __float2half_rn(c[mt][nt][1]));
                *reinterpret_cast<uint32_t*>(Ch + (size_t)(row + 8) * Nn + col) =
                    pkh2(__float2half_rn(c[mt][nt][2]), __float2half_rn(c[mt][nt][3]));
            } else {
                *reinterpret_cast<float2*>(Cf + (size_t)row * Nn + col) =
                    make_float2(c[mt][nt][0], c[mt][nt][1]);
                *reinterpret_cast<float2*>(Cf + (size_t)(row + 8) * Nn + col) =
                    make_float2(c[mt][nt][2], c[mt][nt][3]);
            }
        }
    }
}

// ---------------------------------------------------------------------------
// Attention: one CTA per (b, blk, h). fp16 QKV in, single-pass fp16 mma,
// causal triangular skipping. smem: sQ/sK/sV each [128][128] fp16 = 96KB.
// Warp w owns query rows [16w, 16w+16): QK^T only needs key tiles
// nt < 2w+2; PV only needs key blocks kk < w+1.
// ---------------------------------------------------------------------------
__global__ void __launch_bounds__(256, 1) attn_kernel(
    const __half* __restrict__ qkv, __half* __restrict__ att)
{
    extern __shared__ char smem[];
    __half* sQ = reinterpret_cast<__half*>(smem);            // [128][128]
    __half* sK = reinterpret_cast<__half*>(smem) + 16384;
    __half* sV = reinterpret_cast<__half*>(smem) + 32768;

    const int tid  = threadIdx.x;
    const int lane = tid & 31;
    const int wid  = tid >> 5;

    const int cta = blockIdx.x;
    const int h   = cta & 15;
    const int blk = (cta >> 4) & 63;
    const int b   = cta >> 10;
    const size_t t0 = (size_t)b * TSEQ + (size_t)blk * 128;

    // load Q,K,V: 3 tensors x 128 rows x 16 chunks(16B) = 6144 tasks
#pragma unroll
    for (int t = 0; t < 24; t++) {
        int idx = tid + t * 256;
        int tensor = idx >> 11;          // 0..2
        int rem = idx & 2047;
        int r  = rem >> 4;
        int ch = rem & 15;
        const __half* g = qkv + (t0 + r) * (size_t)N_QKV
                        + tensor * CDIM + h * DHEAD + ch * 8;
        __half* dstb = (tensor == 0) ? sQ : (tensor == 1) ? sK : sV;
        cp16s(smem_u32(dstb + r * 128 + ((ch ^ (r & 7)) * 8)), g);
    }
    cp_commit();
    cp_wait<0>();
    __syncthreads();

    // ----- S = Q K^T (warp tile 16 x 128), causal-skipped -----
    const int rw0  = wid * 16;
    const int nmax = 2 * wid + 2;        // key tiles needed (n8 granularity)

    float s[16][4];
#pragma unroll
    for (int nt = 0; nt < 16; nt++)
#pragma unroll
        for (int e = 0; e < 4; e++) s[nt][e] = 0.f;

#pragma unroll
    for (int kk = 0; kk < 8; kk++) {
        uint32_t q[4];
        {
            int r  = rw0 + (lane & 15);
            int ch = kk * 2 + (lane >> 4);
            int sw = ch ^ (r & 7);
            ldsm4a(q, smem_u32(sQ + r * 128 + sw * 8));
        }
        for (int nt = 0; nt < nmax; nt++) {
            uint32_t k[2];
            int l16  = lane & 15;
            int nrow = nt * 8 + (l16 & 7);
            int ch   = kk * 2 + (l16 >> 3);
            int sw   = ch ^ (nrow & 7);
            ldsm2a(k, smem_u32(sK + nrow * 128 + sw * 8));
            mma_h(s[nt], q, k);
        }
    }

    // ----- causal softmax (over valid tiles only) -----
    const float scale = 0.08838834764831845f;  // 1/sqrt(128)
    const int g  = lane >> 2;
    const int tq = lane & 3;
    const int r0 = rw0 + g;
    const int r1 = r0 + 8;

    float mx0 = -1e30f, mx1 = -1e30f;
    for (int nt = 0; nt < nmax; nt++) {
        int j0 = nt * 8 + tq * 2;
        int j1 = j0 + 1;
        float v;
        v = s[nt][0] * scale; if (j0 > r0) v = -1e30f; s[nt][0] = v; mx0 = fmaxf(mx0, v);
        v = s[nt][1] * scale; if (j1 > r0) v = -1e30f; s[nt][1] = v; mx0 = fmaxf(mx0, v);
        v = s[nt][2] * scale; if (j0 > r1) v = -1e30f; s[nt][2] = v; mx1 = fmaxf(mx1, v);
        v = s[nt][3] * scale; if (j1 > r1) v = -1e30f; s[nt][3] = v; mx1 = fmaxf(mx1, v);
    }
    mx0 = fmaxf(mx0, __shfl_xor_sync(0xffffffffu, mx0, 1));
    mx0 = fmaxf(mx0, __shfl_xor_sync(0xffffffffu, mx0, 2));
    mx1 = fmaxf(mx1, __shfl_xor_sync(0xffffffffu, mx1, 1));
    mx1 = fmaxf(mx1, __shfl_xor_sync(0xffffffffu, mx1, 2));

    float sum0 = 0.f, sum1 = 0.f;
    for (int nt = 0; nt < nmax; nt++) {
        s[nt][0] = __expf(s[nt][0] - mx0); sum0 += s[nt][0];
        s[nt][1] = __expf(s[nt][1] - mx0); sum0 += s[nt][1];
        s[nt][2] = __expf(s[nt][2] - mx1); sum1 += s[nt][2];
        s[nt][3] = __expf(s[nt][3] - mx1); sum1 += s[nt][3];
    }
    sum0 += __shfl_xor_sync(0xffffffffu, sum0, 1);
    sum0 += __shfl_xor_sync(0xffffffffu, sum0, 2);
    sum1 += __shfl_xor_sync(0xffffffffu, sum1, 1);
    sum1 += __shfl_xor_sync(0xffffffffu, sum1, 2);
    const float inv0 = 1.f / sum0;
    const float inv1 = 1.f / sum1;

    // ----- O = P V (P -> fp16 frags), key blocks kk < wid+1 -----
    float o[16][4];
#pragma unroll
    for (int nt = 0; nt < 16; nt++)
#pragma unroll
        for (int e = 0; e < 4; e++) o[nt][e] = 0.f;

    const int kmax = wid + 1;
    for (int kk = 0; kk < kmax; kk++) {
        uint32_t aP[4];
        aP[0] = pkh2(__float2half_rn(s[2 * kk][0]),     __float2half_rn(s[2 * kk][1]));
        aP[1] = pkh2(__float2half_rn(s[2 * kk][2]),     __float2half_rn(s[2 * kk][3]));
        aP[2] = pkh2(__float2half_rn(s[2 * kk + 1][0]), __float2half_rn(s[2 * kk + 1][1]));
        aP[3] = pkh2(__float2half_rn(s[2 * kk + 1][2]), __float2half_rn(s[2 * kk + 1][3]));
#pragma unroll
        for (int nt = 0; nt < 16; nt++) {
            uint32_t v[2];
            int l16  = lane & 15;
            int krow = kk * 16 + l16;
            int sw   = nt ^ (krow & 7);
            ldsm2ta(v, smem_u32(sV + krow * 128 + sw * 8));
            mma_h(o[nt], aP, v);
        }
    }

    // ----- epilogue: fp16 (input to proj GEMM) -----
    const size_t tok0 = t0 + r0;
    const size_t tok1 = t0 + r1;
#pragma unroll
    for (int nt = 0; nt < 16; nt++) {
        int col = h * DHEAD + nt * 8 + tq * 2;
        *reinterpret_cast<uint32_t*>(att + tok0 * CDIM + col) =
            pkh2(__float2half_rn(o[nt][0] * inv0), __float2half_rn(o[nt][1] * inv0));
        *reinterpret_cast<uint32_t*>(att + tok1 * CDIM + col) =
            pkh2(__float2half_rn(o[nt][2] * inv1), __float2half_rn(o[nt][3] * inv1));
    }
}

// ---------------------------------------------------------------------------
// Host launcher
// ---------------------------------------------------------------------------
extern "C" void kernel_launch(void* const* d_in, const int* in_sizes, int n_in,
                              void* d_out, int out_size) {
    const float* x  = (const float*)d_in[0];
    const float* wq = (const float*)d_in[1];
    const float* wp = (const float*)d_in[2];
    float* out = (float*)d_out;

    void *pX, *pWq, *pWp, *pQKV, *pA;
    cudaGetSymbolAddress(&pX,   g_X);
    cudaGetSymbolAddress(&pWq,  g_Wq);
    cudaGetSymbolAddress(&pWp,  g_Wp);
    cudaGetSymbolAddress(&pQKV, g_QKV);
    cudaGetSymbolAddress(&pA,   g_A);

    cudaFuncSetAttribute((const void*)gemm_fp16<true>,
                         cudaFuncAttributeMaxDynamicSharedMemorySize, G_SMEM);
    cudaFuncSetAttribute((const void*)gemm_fp16<false>,
                         cudaFuncAttributeMaxDynamicSharedMemorySize, G_SMEM);
    cudaFuncSetAttribute((const void*)attn_kernel,
                         cudaFuncAttributeMaxDynamicSharedMemorySize, 98304);

    // 1) X, Wq, Wp -> fp16
    {
        int n4 = (MROWS * CDIM) / 4;
        cvt_h_kernel<<<n4 / 256, 256>>>((const float4*)x, (uint32_t*)pX, n4);
    }
    {
        int n4 = (CDIM * N_QKV) / 4;
        cvt_h_kernel<<<n4 / 256, 256>>>((const float4*)wq, (uint32_t*)pWq, n4);
    }
    {
        int n4 = (CDIM * CDIM) / 4;
        cvt_h_kernel<<<n4 / 256, 256>>>((const float4*)wp, (uint32_t*)pWp, n4);
    }

    // 2) QKV = X @ Wq -> fp16
    {
        dim3 grid(N_QKV / 128, MROWS / 128);  // (48, 256)
        gemm_fp16<true><<<grid, 128, G_SMEM>>>(
            (const __half*)pX, (const __half*)pWq, nullptr, (__half*)pQKV,
            N_QKV, CDIM);
    }

    // 3) blocked causal attention -> fp16
    attn_kernel<<<BATCH * NBLK * NHEAD, 256, 98304>>>(
        (const __half*)pQKV, (__half*)pA);

    // 4) Y = A @ Wp -> fp32 final output
    {
        dim3 grid(CDIM / 128, MROWS / 128);   // (16, 256)
        gemm_fp16<false><<<grid, 128, G_SMEM>>>(
            (const __half*)pA, (const __half*)pWp, out, nullptr, CDIM, CDIM);
    }
}

// round 11
// speedup vs baseline: 3.2063x; 1.0075x over previous
#include <cuda_runtime.h>
#include <cuda_bf16.h>
#include <cuda_fp16.h>
#include <cstdint>
#include <cstddef>

// ---------------------------------------------------------------------------
// Problem constants
// ---------------------------------------------------------------------------
constexpr int BATCH = 4;
constexpr int TSEQ  = 8192;
constexpr int CDIM  = 2048;
constexpr int DHEAD = 128;
constexpr int NBLK  = 64;            // TSEQ / 128
constexpr int MROWS = BATCH * TSEQ;  // 32768
constexpr int N_QKV = 3 * CDIM;      // 6144
constexpr int NHEAD = 16;

// ---------------------------------------------------------------------------
// Static scratch (no allocations allowed)
// ---------------------------------------------------------------------------
__device__ __align__(256) __half g_X  [(size_t)MROWS * CDIM];
__device__ __align__(256) __half g_Wq [(size_t)CDIM * N_QKV];   // [K][N] native
__device__ __align__(256) __half g_Wp [(size_t)CDIM * CDIM];    // [K][N] native
__device__ __align__(256) __half g_QKV[(size_t)MROWS * N_QKV];  // fp16 intermediates
__device__ __align__(256) __half g_A  [(size_t)MROWS * CDIM];

// ---------------------------------------------------------------------------
// Helpers
// ---------------------------------------------------------------------------
__device__ __forceinline__ uint32_t smem_u32(const void* p) {
    return (uint32_t)__cvta_generic_to_shared(p);
}
__device__ __forceinline__ void cp16s(uint32_t s, const void* g) {
    asm volatile("cp.async.cg.shared.global [%0], [%1], 16;" :: "r"(s), "l"(g));
}
__device__ __forceinline__ void cp_commit() {
    asm volatile("cp.async.commit_group;");
}
template <int N>
__device__ __forceinline__ void cp_wait() {
    asm volatile("cp.async.wait_group %0;" :: "n"(N));
}

__device__ __forceinline__ uint32_t pkh2(__half a, __half b) {
    __half2 t; t.x = a; t.y = b;
    return *reinterpret_cast<uint32_t*>(&t);
}

__device__ __forceinline__ void ldsm4a(uint32_t* d, uint32_t a) {
    asm volatile("ldmatrix.sync.aligned.m8n8.x4.shared.b16 {%0,%1,%2,%3}, [%4];"
                 : "=r"(d[0]), "=r"(d[1]), "=r"(d[2]), "=r"(d[3]) : "r"(a));
}
__device__ __forceinline__ void ldsm4ta(uint32_t* d, uint32_t a) {
    asm volatile("ldmatrix.sync.aligned.m8n8.x4.trans.shared.b16 {%0,%1,%2,%3}, [%4];"
                 : "=r"(d[0]), "=r"(d[1]), "=r"(d[2]), "=r"(d[3]) : "r"(a));
}
__device__ __forceinline__ void ldsm2a(uint32_t* d, uint32_t a) {
    asm volatile("ldmatrix.sync.aligned.m8n8.x2.shared.b16 {%0,%1}, [%2];"
                 : "=r"(d[0]), "=r"(d[1]) : "r"(a));
}
__device__ __forceinline__ void ldsm2ta(uint32_t* d, uint32_t a) {
    asm volatile("ldmatrix.sync.aligned.m8n8.x2.trans.shared.b16 {%0,%1}, [%2];"
                 : "=r"(d[0]), "=r"(d[1]) : "r"(a));
}
// fp16 mma
__device__ __forceinline__ void mma_h(float* c, const uint32_t* a, const uint32_t* b) {
    asm volatile(
        "mma.sync.aligned.m16n8k16.row.col.f32.f16.f16.f32 "
        "{%0,%1,%2,%3}, {%4,%5,%6,%7}, {%8,%9}, {%0,%1,%2,%3};"
        : "+f"(c[0]), "+f"(c[1]), "+f"(c[2]), "+f"(c[3])
        : "r"(a[0]), "r"(a[1]), "r"(a[2]), "r"(a[3]), "r"(b[0]), "r"(b[1]));
}

// ---------------------------------------------------------------------------
// fp32 -> fp16 (single, RN)
// ---------------------------------------------------------------------------
__global__ void cvt_h_kernel(const float4* __restrict__ src,
                             uint32_t* __restrict__ dst, int n4) {
    int i = blockIdx.x * blockDim.x + threadIdx.x;
    if (i >= n4) return;
    float4 v = src[i];
    dst[2 * i]     = pkh2(__float2half_rn(v.x), __float2half_rn(v.y));
    dst[2 * i + 1] = pkh2(__float2half_rn(v.z), __float2half_rn(v.w));
}

// ---------------------------------------------------------------------------
// fp16 single-pass GEMM: C[M,N] = A[M,K] @ B[K,N]
// BM=128, BN=128, BK=64, 3-stage cp.async ring.
// 128 threads = 4 warps (2m x 2n), warp tile 64x64, 2 CTAs/SM.
// Register-level software pipeline: fragments for k16 step kk+1 are loaded
// while the mma block of step kk executes (double-buffered aa/bb).
// Stage layout (32768 B): A @0 (16KB: 128 rows x 128B SW128),
//                         B @16384 (16KB: 64 krows x 256B).
// OUT_HALF: write fp16 pairs to Ch; else fp32 to Cf.
// ---------------------------------------------------------------------------
constexpr int G_STAGE = 32768;
constexpr int G_BOFF  = 16384;
constexpr int G_SMEM  = 3 * G_STAGE;  // 98304

template <bool OUT_HALF>
__global__ void __launch_bounds__(128, 2) gemm_fp16(
    const __half* __restrict__ A, const __half* __restrict__ B,
    float* __restrict__ Cf, __half* __restrict__ Ch, int Nn, int Kk)
{
    extern __shared__ char smem[];
    const uint32_t sbase = smem_u32(smem);
    const int tid  = threadIdx.x;
    const int lane = tid & 31;
    const int wid  = tid >> 5;
    const int m0   = blockIdx.y * 128;
    const int n0   = blockIdx.x * 128;
    const int wm   = (wid >> 1) * 64;
    const int wn   = (wid & 1) * 64;

    // --- load geometry (base + stride; swizzle bits invariant under row step) ---
    const int ra = tid >> 3, ca = tid & 7;
    const char* gA0 = (const char*)(A + (size_t)(m0 + ra) * Kk + ca * 8);
    const uint32_t sA0 = sbase + ra * 128 + ((ca ^ (ra & 7)) * 16);
    const size_t rowA = (size_t)16 * Kk * 2;       // +16 rows
    const int rb = tid >> 4, cb = tid & 15;
    const char* gB0 = (const char*)(B + (size_t)rb * Nn + n0 + cb * 8);
    const uint32_t sB0 = sbase + G_BOFF + rb * 256 + ((cb ^ (rb & 7)) * 16);
    const size_t rowB = (size_t)8 * Nn * 2;        // +8 krows

    const size_t stepA = 128;                      // k-tile: 64 halfs
    const size_t stepB = (size_t)64 * Nn * 2;

    const int NK = Kk / 64;

    // per-warp fragment smem base addresses (kk-dependent parts added later)
    const uint32_t aAdr0 = sbase + (wm + (lane & 15)) * 128
                         + (((lane >> 4) ^ ((wm + (lane & 15)) & 7)) * 16);
    // Note: swizzle depends on kk (ch = kk*2 + hi); recompute per use below.

    // prologue: stages 0..1
#pragma unroll
    for (int s = 0; s < 2; s++) {
        uint32_t so = (uint32_t)(s * G_STAGE);
        const char* ga = gA0 + (size_t)s * stepA;
        const char* gb = gB0 + (size_t)s * stepB;
#pragma unroll
        for (int i = 0; i < 8; i++)
            cp16s(sA0 + so + i * (16 * 128), ga + (size_t)i * rowA);
#pragma unroll
        for (int i = 0; i < 8; i++)
            cp16s(sB0 + so + i * (8 * 256), gb + (size_t)i * rowB);
        cp_commit();
    }

    float c[4][8][4];
#pragma unroll
    for (int mt = 0; mt < 4; mt++)
#pragma unroll
        for (int nt = 0; nt < 8; nt++)
#pragma unroll
            for (int e = 0; e < 4; e++) c[mt][nt][e] = 0.f;

    uint32_t aa[2][4][4], bb[2][4][4];

    // fragment loader for k16 step kk from stage buffer sbuf
    auto load_frags = [&](uint32_t sbuf, int kk, int buf) {
#pragma unroll
        for (int p = 0; p < 4; p++) {
            int krow = kk * 16 + (lane & 15);
            int ch   = (wn >> 3) + p * 2 + (lane >> 4);
            int sw   = ch ^ (krow & 7);
            ldsm4ta(bb[buf][p], sbuf + G_BOFF + krow * 256 + sw * 16);
        }
#pragma unroll
        for (int mt = 0; mt < 4; mt++) {
            int r  = wm + mt * 16 + (lane & 15);
            int ch = kk * 2 + (lane >> 4);
            int sw = ch ^ (r & 7);
            ldsm4a(aa[buf][mt], sbuf + r * 128 + sw * 16);
        }
    };

    int sidx = 0;                            // stage index of kt
    for (int kt = 0; kt < NK; kt++) {
        cp_wait<1>();
        __syncthreads();

        const uint32_t sbuf = sbase + sidx * G_STAGE;

        // start fragment loads for kk=0 immediately (fill LSU early)
        load_frags(sbuf, 0, 0);

        // issue stage kt+2 (buffer last consumed in iter kt-1; safe after barrier)
        {
            int kn = kt + 2;
            if (kn < NK) {
                int sn = sidx + 2; if (sn >= 3) sn -= 3;
                uint32_t so = (uint32_t)(sn * G_STAGE);
                const char* ga = gA0 + (size_t)kn * stepA;
                const char* gb = gB0 + (size_t)kn * stepB;
#pragma unroll
                for (int i = 0; i < 8; i++)
                    cp16s(sA0 + so + i * (16 * 128), ga + (size_t)i * rowA);
#pragma unroll
                for (int i = 0; i < 8; i++)
                    cp16s(sB0 + so + i * (8 * 256), gb + (size_t)i * rowB);
            }
            cp_commit();
        }

#pragma unroll
        for (int kk = 0; kk < 4; kk++) {
            const int buf = kk & 1;
            // prefetch next step's fragments before consuming current ones
            if (kk < 3) load_frags(sbuf, kk + 1, buf ^ 1);
#pragma unroll
            for (int mt = 0; mt < 4; mt++)
#pragma unroll
                for (int p = 0; p < 4; p++) {
                    mma_h(c[mt][2 * p],     aa[buf][mt], &bb[buf][p][0]);
                    mma_h(c[mt][2 * p + 1], aa[buf][mt], &bb[buf][p][2]);
                }
        }
        sidx++; if (sidx >= 3) sidx = 0;
    }
    (void)aAdr0;

    // epilogue
#pragma unroll
    for (int mt = 0; mt < 4; mt++) {
#pragma unroll
        for (int nt = 0; nt < 8; nt++) {
            int row = m0 + wm + mt * 16 + (lane >> 2);
            int col = n0 + wn + nt * 8 + (lane & 3) * 2;
            if (OUT_HALF) {
                *reinterpret_cast<uint32_t*>(Ch + (size_t)row * Nn + col) =
                    pkh2(__float2half_rn(c[mt][nt][0]), __float2half_rn(c[mt][nt][1]));
                *reinterpret_cast<uint32_t*>(Ch + (size_t)(row + 8) * Nn + col) =
                    pkh2(__float2half_rn(c[mt][nt][2]), __float2half_rn(c[mt][nt][3]));
            } else {
                *reinterpret_cast<float2*>(Cf + (size_t)row * Nn + col) =
                    make_float2(c[mt][nt][0], c[mt][nt][1]);
                *reinterpret_cast<float2*>(Cf + (size_t)(row + 8) * Nn + col) =
                    make_float2(c[mt][nt][2], c[mt][nt][3]);
            }
        }
    }
}

// ---------------------------------------------------------------------------
// Attention: one CTA per (b, blk, h). fp16 QKV in, single-pass fp16 mma,
// causal triangular skipping. smem: sQ/sK/sV each [128][128] fp16 = 96KB.
// ---------------------------------------------------------------------------
__global__ void __launch_bounds__(256, 1) attn_kernel(
    const __half* __restrict__ qkv, __half* __restrict__ att)
{
    extern __shared__ char smem[];
    __half* sQ = reinterpret_cast<__half*>(smem);            // [128][128]
    __half* sK = reinterpret_cast<__half*>(smem) + 16384;
    __half* sV = reinterpret_cast<__half*>(smem) + 32768;

    const int tid  = threadIdx.x;
    const int lane = tid & 31;
    const int wid  = tid >> 5;

    const int cta = blockIdx.x;
    const int h   = cta & 15;
    const int blk = (cta >> 4) & 63;
    const int b   = cta >> 10;
    const size_t t0 = (size_t)b * TSEQ + (size_t)blk * 128;

    // load Q,K,V: 3 tensors x 128 rows x 16 chunks(16B) = 6144 tasks
#pragma unroll
    for (int t = 0; t < 24; t++) {
        int idx = tid + t * 256;
        int tensor = idx >> 11;          // 0..2
        int rem = idx & 2047;
        int r  = rem >> 4;
        int ch = rem & 15;
        const __half* g = qkv + (t0 + r) * (size_t)N_QKV
                        + tensor * CDIM + h * DHEAD + ch * 8;
        __half* dstb = (tensor == 0) ? sQ : (tensor == 1) ? sK : sV;
        cp16s(smem_u32(dstb + r * 128 + ((ch ^ (r & 7)) * 8)), g);
    }
    cp_commit();
    cp_wait<0>();
    __syncthreads();

    // ----- S = Q K^T (warp tile 16 x 128), causal-skipped -----
    const int rw0  = wid * 16;
    const int nmax = 2 * wid + 2;        // key tiles needed (n8 granularity)

    float s[16][4];
#pragma unroll
    for (int nt = 0; nt < 16; nt++)
#pragma unroll
        for (int e = 0; e < 4; e++) s[nt][e] = 0.f;

#pragma unroll
    for (int kk = 0; kk < 8; kk++) {
        uint32_t q[4];
        {
            int r  = rw0 + (lane & 15);
            int ch = kk * 2 + (lane >> 4);
            int sw = ch ^ (r & 7);
            ldsm4a(q, smem_u32(sQ + r * 128 + sw * 8));
        }
        for (int nt = 0; nt < nmax; nt++) {
            uint32_t k[2];
            int l16  = lane & 15;
            int nrow = nt * 8 + (l16 & 7);
            int ch   = kk * 2 + (l16 >> 3);
            int sw   = ch ^ (nrow & 7);
            ldsm2a(k, smem_u32(sK + nrow * 128 + sw * 8));
            mma_h(s[nt], q, k);
        }
    }

    // ----- causal softmax (over valid tiles only) -----
    const float scale = 0.08838834764831845f;  // 1/sqrt(128)
    const int g  = lane >> 2;
    const int tq = lane & 3;
    const int r0 = rw0 + g;
    const int r1 = r0 + 8;

    float mx0 = -1e30f, mx1 = -1e30f;
    for (int nt = 0; nt < nmax; nt++) {
        int j0 = nt * 8 + tq * 2;
        int j1 = j0 + 1;
        float v;
        v = s[nt][0] * scale; if (j0 > r0) v = -1e30f; s[nt][0] = v; mx0 = fmaxf(mx0, v);
        v = s[nt][1] * scale; if (j1 > r0) v = -1e30f; s[nt][1] = v; mx0 = fmaxf(mx0, v);
        v = s[nt][2] * scale; if (j0 > r1) v = -1e30f; s[nt][2] = v; mx1 = fmaxf(mx1, v);
        v = s[nt][3] * scale; if (j1 > r1) v = -1e30f; s[nt][3] = v; mx1 = fmaxf(mx1, v);
    }
    mx0 = fmaxf(mx0, __shfl_xor_sync(0xffffffffu, mx0, 1));
    mx0 = fmaxf(mx0, __shfl_xor_sync(0xffffffffu, mx0, 2));
    mx1 = fmaxf(mx1, __shfl_xor_sync(0xffffffffu, mx1, 1));
    mx1 = fmaxf(mx1, __shfl_xor_sync(0xffffffffu, mx1, 2));

    float sum0 = 0.f, sum1 = 0.f;
    for (int nt = 0; nt < nmax; nt++) {
        s[nt][0] = __expf(s[nt][0] - mx0); sum0 += s[nt][0];
        s[nt][1] = __expf(s[nt][1] - mx0); sum0 += s[nt][1];
        s[nt][2] = __expf(s[nt][2] - mx1); sum1 += s[nt][2];
        s[nt][3] = __expf(s[nt][3] - mx1); sum1 += s[nt][3];
    }
    sum0 += __shfl_xor_sync(0xffffffffu, sum0, 1);
    sum0 += __shfl_xor_sync(0xffffffffu, sum0, 2);
    sum1 += __shfl_xor_sync(0xffffffffu, sum1, 1);
    sum1 += __shfl_xor_sync(0xffffffffu, sum1, 2);
    const float inv0 = 1.f / sum0;
    const float inv1 = 1.f / sum1;

    // ----- O = P V (P -> fp16 frags), key blocks kk < wid+1 -----
    float o[16][4];
#pragma unroll
    for (int nt = 0; nt < 16; nt++)
#pragma unroll
        for (int e = 0; e < 4; e++) o[nt][e] = 0.f;

    const int kmax = wid + 1;
    for (int kk = 0; kk < kmax; kk++) {
        uint32_t aP[4];
        aP[0] = pkh2(__float2half_rn(s[2 * kk][0]),     __float2half_rn(s[2 * kk][1]));
        aP[1] = pkh2(__float2half_rn(s[2 * kk][2]),     __float2half_rn(s[2 * kk][3]));
        aP[2] = pkh2(__float2half_rn(s[2 * kk + 1][0]), __float2half_rn(s[2 * kk + 1][1]));
        aP[3] = pkh2(__float2half_rn(s[2 * kk + 1][2]), __float2half_rn(s[2 * kk + 1][3]));
#pragma unroll
        for (int nt = 0; nt < 16; nt++) {
            uint32_t v[2];
            int l16  = lane & 15;
            int krow = kk * 16 + l16;
            int sw   = nt ^ (krow & 7);
            ldsm2ta(v, smem_u32(sV + krow * 128 + sw * 8));
            mma_h(o[nt], aP, v);
        }
    }

    // ----- epilogue: fp16 (input to proj GEMM) -----
    const size_t tok0 = t0 + r0;
    const size_t tok1 = t0 + r1;
#pragma unroll
    for (int nt = 0; nt < 16; nt++) {
        int col = h * DHEAD + nt * 8 + tq * 2;
        *reinterpret_cast<uint32_t*>(att + tok0 * CDIM + col) =
            pkh2(__float2half_rn(o[nt][0] * inv0), __float2half_rn(o[nt][1] * inv0));
        *reinterpret_cast<uint32_t*>(att + tok1 * CDIM + col) =
            pkh2(__float2half_rn(o[nt][2] * inv1), __float2half_rn(o[nt][3] * inv1));
    }
}

// ---------------------------------------------------------------------------
// Host launcher
// ---------------------------------------------------------------------------
extern "C" void kernel_launch(void* const* d_in, const int* in_sizes, int n_in,
                              void* d_out, int out_size) {
    const float* x  = (const float*)d_in[0];
    const float* wq = (const float*)d_in[1];
    const float* wp = (const float*)d_in[2];
    float* out = (float*)d_out;

    void *pX, *pWq, *pWp, *pQKV, *pA;
    cudaGetSymbolAddress(&pX,   g_X);
    cudaGetSymbolAddress(&pWq,  g_Wq);
    cudaGetSymbolAddress(&pWp,  g_Wp);
    cudaGetSymbolAddress(&pQKV, g_QKV);
    cudaGetSymbolAddress(&pA,   g_A);

    cudaFuncSetAttribute((const void*)gemm_fp16<true>,
                         cudaFuncAttributeMaxDynamicSharedMemorySize, G_SMEM);
    cudaFuncSetAttribute((const void*)gemm_fp16<false>,
                         cudaFuncAttributeMaxDynamicSharedMemorySize, G_SMEM);
    cudaFuncSetAttribute((const void*)attn_kernel,
                         cudaFuncAttributeMaxDynamicSharedMemorySize, 98304);

    // 1) X, Wq, Wp -> fp16
    {
        int n4 = (MROWS * CDIM) / 4;
        cvt_h_kernel<<<n4 / 256, 256>>>((const float4*)x, (uint32_t*)pX, n4);
    }
    {
        int n4 = (CDIM * N_QKV) / 4;
        cvt_h_kernel<<<n4 / 256, 256>>>((const float4*)wq, (uint32_t*)pWq, n4);
    }
    {
        int n4 = (CDIM * CDIM) / 4;
        cvt_h_kernel<<<n4 / 256, 256>>>((const float4*)wp, (uint32_t*)pWp, n4);
    }

    // 2) QKV = X @ Wq -> fp16
    {
        dim3 grid(N_QKV / 128, MROWS / 128);  // (48, 256)
        gemm_fp16<true><<<grid, 128, G_SMEM>>>(
            (const __half*)pX, (const __half*)pWq, nullptr, (__half*)pQKV,
            N_QKV, CDIM);
    }

    // 3) blocked causal attention -> fp16
    attn_kernel<<<BATCH * NBLK * NHEAD, 256, 98304>>>(
        (const __half*)pQKV, (__half*)pA);

    // 4) Y = A @ Wp -> fp32 final output
    {
        dim3 grid(CDIM / 128, MROWS / 128);   // (16, 256)
        gemm_fp16<false><<<grid, 128, G_SMEM>>>(
            (const __half*)pA, (const __half*)pWp, out, nullptr, CDIM, CDIM);
    }
}